// round 10
// baseline (speedup 1.0000x reference)
#include <cuda_runtime.h>
#include <cuda_bf16.h>
#include <math.h>
#include <stdint.h>

#define BB 2
#define SS 2048
#define DD 2048
#define HH 16
#define QPd 1024
#define KVPd 1365
#define CKVN 1429
#define FFd 8192
#define MMr 4096
#define KVL_PAD 1408
#define DKV_NPAD 1536

typedef __nv_bfloat16 bf16;

// ---- fp32 scratch ----
__device__ float g_cq[(size_t)MMr * QPd];
__device__ float g_qraw[(size_t)MMr * DD];
__device__ float g_kvraw[(size_t)MMr * 3072];
__device__ float g_q[(size_t)MMr * DD];
__device__ float g_k[(size_t)MMr * DD];
__device__ float g_v[(size_t)MMr * DD];
__device__ float g_x2[(size_t)MMr * DD];
__device__ float g_freqs[32];

// ---- bf16 hi/lo activations ----
__device__ bf16 g_hh[(size_t)MMr * DD];
__device__ bf16 g_hl[(size_t)MMr * DD];
__device__ bf16 g_cqh[(size_t)MMr * QPd];
__device__ bf16 g_cql[(size_t)MMr * QPd];
__device__ bf16 g_kvlh[(size_t)MMr * KVL_PAD];
__device__ bf16 g_kvll[(size_t)MMr * KVL_PAD];
__device__ bf16 g_oh[(size_t)MMr * DD];
__device__ bf16 g_ol[(size_t)MMr * DD];
__device__ bf16 g_ff1h[(size_t)MMr * FFd];
__device__ bf16 g_ff1l[(size_t)MMr * FFd];

// ---- bf16 hi/lo weights, [N,K] layout ----
__device__ bf16 g_dqTh[(size_t)QPd * DD];
__device__ bf16 g_dqTl[(size_t)QPd * DD];
__device__ bf16 g_dkvTh[(size_t)DKV_NPAD * DD];
__device__ bf16 g_dkvTl[(size_t)DKV_NPAD * DD];
__device__ bf16 g_uqTh[(size_t)DD * QPd];
__device__ bf16 g_uqTl[(size_t)DD * QPd];
__device__ bf16 g_ukvTh[(size_t)3072 * KVL_PAD];
__device__ bf16 g_ukvTl[(size_t)3072 * KVL_PAD];
__device__ bf16 g_w1Th[(size_t)FFd * DD];
__device__ bf16 g_w1Tl[(size_t)FFd * DD];
__device__ bf16 g_w2Th[(size_t)DD * FFd];
__device__ bf16 g_w2Tl[(size_t)DD * FFd];
__device__ bf16 g_woCh[(size_t)DD * DD];
__device__ bf16 g_woCl[(size_t)DD * DD];

__device__ __forceinline__ void hilo(float v, bf16& h, bf16& l) {
    h = __float2bfloat16_rn(v);
    l = __float2bfloat16_rn(v - __bfloat162float(h));
}
__device__ __forceinline__ uint32_t f2tf(float x) {
    uint32_t u;
    asm("cvt.rna.tf32.f32 %0, %1;" : "=r"(u) : "f"(x));
    return u;
}
__device__ __forceinline__ float rtf(float x) { return __uint_as_float(f2tf(x)); }

__device__ __forceinline__ void mma_tf32(float* c, const uint32_t* a, uint32_t b0, uint32_t b1) {
    asm volatile(
        "mma.sync.aligned.m16n8k8.row.col.f32.tf32.tf32.f32 "
        "{%0,%1,%2,%3}, {%4,%5,%6,%7}, {%8,%9}, {%0,%1,%2,%3};"
        : "+f"(c[0]), "+f"(c[1]), "+f"(c[2]), "+f"(c[3])
        : "r"(a[0]), "r"(a[1]), "r"(a[2]), "r"(a[3]), "r"(b0), "r"(b1));
}
__device__ __forceinline__ void mma_bf16(float* c, const uint32_t* a, uint32_t b0, uint32_t b1) {
    asm volatile(
        "mma.sync.aligned.m16n8k16.row.col.f32.bf16.bf16.f32 "
        "{%0,%1,%2,%3}, {%4,%5,%6,%7}, {%8,%9}, {%0,%1,%2,%3};"
        : "+f"(c[0]), "+f"(c[1]), "+f"(c[2]), "+f"(c[3])
        : "r"(a[0]), "r"(a[1]), "r"(a[2]), "r"(a[3]), "r"(b0), "r"(b1));
}
__device__ __forceinline__ void cp16b(bf16* dst, const bf16* src) {
    uint32_t d = (uint32_t)__cvta_generic_to_shared(dst);
    asm volatile("cp.async.cg.shared.global [%0], [%1], 16;" :: "r"(d), "l"(src));
}

// ================= split-bf16 GEMM =================
// C[M,N] = A @ B^T with A=[M,K] (Ah+Al), B=[N,K] (Bh+Bl); 3 K-phases:
// Ah*Bh + Al*Bh + Ah*Bl.  CTA tile 256x128, warp 64x64, BK=64.
#define BM2 256
#define BN2 128
#define BK2 64
#define AST 72
#define ASE (BM2 * AST)
#define BSE (BN2 * AST)
#define GEMM2_SMEM ((ASE + BSE) * 2 * 2)

// EPI: 0 fp32 C ; 1 bias+GELU -> hi/lo bf16 ; 2 (+bias)+res -> fp32
template <int EPI>
__global__ __launch_bounds__(256) void gemm_bf(
    const bf16* __restrict__ Ah, const bf16* __restrict__ Al, int lda,
    const bf16* __restrict__ Bh, const bf16* __restrict__ Bl, int ldb,
    float* __restrict__ C, bf16* __restrict__ Ch, bf16* __restrict__ Cl, int ldc,
    int N, int KC,
    const float* __restrict__ bias, const float* __restrict__ res, int ldres)
{
    extern __shared__ bf16 sm2[];
    bf16* As = sm2;              // [2][ASE]
    bf16* Bs = sm2 + 2 * ASE;    // [2][BSE]
    const int tid = threadIdx.x, lane = tid & 31, warp = tid >> 5;
    const int wm = warp >> 1, wn = warp & 1;
    const int bm0 = blockIdx.y * BM2, bn0 = blockIdx.x * BN2;
    const int g = lane >> 2, t = lane & 3;

    float acc[4][8][4];
#pragma unroll
    for (int i = 0; i < 4; i++)
#pragma unroll
        for (int j = 0; j < 8; j++)
#pragma unroll
            for (int c = 0; c < 4; c++) acc[i][j][c] = 0.f;

    const int TC = 3 * KC;
    auto load = [&](int buf, int cc) {
        int ccm = cc;
        if (ccm >= KC) ccm -= KC;
        if (ccm >= KC) ccm -= KC;
        const bf16* Ag = (cc >= KC && cc < 2 * KC) ? Al : Ah;
        const bf16* Bg = (cc >= 2 * KC) ? Bl : Bh;
        const int k0 = ccm * BK2;
        bf16* Ab = As + buf * ASE;
        bf16* Bb = Bs + buf * BSE;
#pragma unroll
        for (int i = 0; i < 8; i++) {
            int idx = i * 256 + tid;
            int r = idx >> 3, s = idx & 7;
            cp16b(Ab + r * AST + s * 8, Ag + (size_t)(bm0 + r) * lda + k0 + s * 8);
        }
#pragma unroll
        for (int i = 0; i < 4; i++) {
            int idx = i * 256 + tid;
            int r = idx >> 3, s = idx & 7;
            cp16b(Bb + r * AST + s * 8, Bg + (size_t)(bn0 + r) * ldb + k0 + s * 8);
        }
        asm volatile("cp.async.commit_group;");
    };

    load(0, 0);
    int buf = 0;
    for (int cc = 0; cc < TC; cc++) {
        if (cc + 1 < TC) {
            load(buf ^ 1, cc + 1);
            asm volatile("cp.async.wait_group 1;");
        } else {
            asm volatile("cp.async.wait_group 0;");
        }
        __syncthreads();
        const bf16* Ab = As + buf * ASE;
        const bf16* Bb = Bs + buf * BSE;
#pragma unroll
        for (int ks = 0; ks < 4; ks++) {
            const int kb = ks * 16;
            uint32_t a[4][4];
#pragma unroll
            for (int im = 0; im < 4; im++) {
                const int r = wm * 64 + im * 16 + g;
                a[im][0] = *(const uint32_t*)(Ab + r * AST + kb + 2 * t);
                a[im][1] = *(const uint32_t*)(Ab + (r + 8) * AST + kb + 2 * t);
                a[im][2] = *(const uint32_t*)(Ab + r * AST + kb + 2 * t + 8);
                a[im][3] = *(const uint32_t*)(Ab + (r + 8) * AST + kb + 2 * t + 8);
            }
#pragma unroll
            for (int nt = 0; nt < 8; nt++) {
                const int c = wn * 64 + nt * 8 + g;
                uint32_t b0 = *(const uint32_t*)(Bb + c * AST + kb + 2 * t);
                uint32_t b1 = *(const uint32_t*)(Bb + c * AST + kb + 2 * t + 8);
#pragma unroll
                for (int im = 0; im < 4; im++) mma_bf16(acc[im][nt], a[im], b0, b1);
            }
        }
        __syncthreads();
        buf ^= 1;
    }

#pragma unroll
    for (int im = 0; im < 4; im++)
#pragma unroll
        for (int nt = 0; nt < 8; nt++) {
            const int r0 = bm0 + wm * 64 + im * 16 + g;
            const int c0 = bn0 + wn * 64 + nt * 8 + 2 * t;
#pragma unroll
            for (int e = 0; e < 4; e++) {
                int r = r0 + (e >> 1) * 8;
                int c = c0 + (e & 1);
                if (c < N) {
                    float v = acc[im][nt][e];
                    if (EPI == 0) {
                        C[(size_t)r * ldc + c] = v;
                    } else if (EPI == 1) {
                        v += bias[c];
                        v = 0.5f * v * (1.f + erff(v * 0.7071067811865475f));
                        bf16 h, l;
                        hilo(v, h, l);
                        Ch[(size_t)r * ldc + c] = h;
                        Cl[(size_t)r * ldc + c] = l;
                    } else {
                        if (bias) v += bias[c];
                        v += res[(size_t)r * ldres + c];
                        C[(size_t)r * ldc + c] = v;
                    }
                }
            }
        }
}

// ================= LayerNorm -> hi/lo bf16 =================
__global__ void ln2_kernel(const float* __restrict__ in, int ldin, int cols,
                           const float* __restrict__ w, const float* __restrict__ b,
                           bf16* __restrict__ oh, bf16* __restrict__ ol, int ldout, int padto)
{
    extern __shared__ float sbuf[];
    __shared__ float red[8];
    __shared__ float bc[2];
    const int row = blockIdx.x, tid = threadIdx.x, lane = tid & 31, warp = tid >> 5;
    const float* ip = in + (size_t)row * ldin;
    float s = 0.f;
    for (int c = tid; c < cols; c += 256) { float v = ip[c]; sbuf[c] = v; s += v; }
#pragma unroll
    for (int o = 16; o > 0; o >>= 1) s += __shfl_xor_sync(0xffffffffu, s, o);
    if (lane == 0) red[warp] = s;
    __syncthreads();
    if (tid == 0) { float t = 0; for (int i = 0; i < 8; i++) t += red[i]; bc[0] = t / cols; }
    __syncthreads();
    float mean = bc[0], vs = 0.f;
    for (int c = tid; c < cols; c += 256) { float d = sbuf[c] - mean; vs += d * d; }
#pragma unroll
    for (int o = 16; o > 0; o >>= 1) vs += __shfl_xor_sync(0xffffffffu, vs, o);
    if (lane == 0) red[warp] = vs;
    __syncthreads();
    if (tid == 0) { float t = 0; for (int i = 0; i < 8; i++) t += red[i]; bc[1] = rsqrtf(t / cols + 1e-5f); }
    __syncthreads();
    float inv = bc[1];
    bf16* oph = oh + (size_t)row * ldout;
    bf16* opl = ol + (size_t)row * ldout;
    for (int c = tid; c < cols; c += 256) {
        float v = (sbuf[c] - mean) * inv * w[c] + b[c];
        bf16 h, l;
        hilo(v, h, l);
        oph[c] = h; opl[c] = l;
    }
    for (int c = cols + tid; c < padto; c += 256) { oph[c] = __float2bfloat16(0.f); opl[c] = __float2bfloat16(0.f); }
}

// ===== weight transpose-convert: in [K,N] fp32 (stride N) -> out [Npad, Kpad] hi/lo bf16 =====
__global__ void tconv_kernel(const float* __restrict__ in, int K, int N, int Kpad,
                             bf16* __restrict__ oh, bf16* __restrict__ ol)
{
    __shared__ float tb[32][33];
    const int k0 = blockIdx.x * 32, n0 = blockIdx.y * 32;
    const int tx = threadIdx.x, ty = threadIdx.y;
#pragma unroll
    for (int i = 0; i < 32; i += 8) {
        int k = k0 + ty + i, n = n0 + tx;
        tb[ty + i][tx] = (k < K && n < N) ? in[(size_t)k * N + n] : 0.f;
    }
    __syncthreads();
#pragma unroll
    for (int i = 0; i < 32; i += 8) {
        int n = n0 + ty + i, k = k0 + tx;
        bf16 h, l;
        hilo(tb[tx][ty + i], h, l);
        oh[(size_t)n * Kpad + k] = h;
        ol[(size_t)n * Kpad + k] = l;
    }
}

// Wo: already [N,K]-contiguous; elementwise convert
__global__ void wocv_kernel(const float* __restrict__ in, bf16* __restrict__ oh, bf16* __restrict__ ol) {
    size_t i = (size_t)blockIdx.x * blockDim.x + threadIdx.x;
    if (i < (size_t)DD * DD) {
        bf16 h, l;
        hilo(in[i], h, l);
        oh[i] = h; ol[i] = l;
    }
}

__global__ void freqs_kernel() {
    int j = threadIdx.x;
    if (j < 32) g_freqs[j] = (float)exp(-(double)j * 0.14391156831212787);
}

__global__ void rope_q_kernel(const float* __restrict__ qraw, float* __restrict__ qout) {
    int bs = blockIdx.x;
    int s = bs & (SS - 1), b = bs >> 11;
    for (int i = threadIdx.x; i < DD; i += 256) {
        int hh = i >> 7, d = i & 127;
        const float* src = qraw + (size_t)bs * DD + hh * 128;
        float v;
        if (d < 64) {
            v = src[d];
        } else {
            int dd = d - 64;
            int j = dd & 31;
            float t = (float)s * g_freqs[j];
            float x = src[64 + dd];
            float rx = (dd < 32) ? -src[64 + dd + 32] : src[64 + dd - 32];
            v = x * cosf(t) + rx * sinf(t);
        }
        qout[(((size_t)b * HH + hh) * SS + s) * 128 + d] = rtf(v);
    }
}

__global__ void reorder_kv_kernel(const float* __restrict__ kvraw, const float* __restrict__ ckv,
                                  float* __restrict__ kout, float* __restrict__ vout) {
    __shared__ float kr[64];
    int bs = blockIdx.x;
    int s = bs & (SS - 1), b = bs >> 11;
    int tid = threadIdx.x;
    if (tid < 64) {
        int dd = tid, j = dd & 31;
        float t = (float)s * g_freqs[j];
        const float* src = ckv + (size_t)bs * CKVN + KVPd;
        float x = src[dd];
        float rx = (dd < 32) ? -src[dd + 32] : src[dd - 32];
        kr[dd] = rtf(x * cosf(t) + rx * sinf(t));
    }
    __syncthreads();
    for (int i = tid; i < HH * 192; i += 256) {
        int hh = i / 192, d = i % 192;
        float v = rtf(kvraw[(size_t)bs * 3072 + i]);
        size_t base = (((size_t)b * HH + hh) * SS + s) * 128;
        if (d < 64) kout[base + d] = v;
        else vout[base + (d - 64)] = v;
    }
    for (int i = tid; i < HH * 64; i += 256) {
        int hh = i >> 6, dd = i & 63;
        kout[(((size_t)b * HH + hh) * SS + s) * 128 + 64 + dd] = kr[dd];
    }
}

// ================= attention (tf32 legacy), outputs hi/lo bf16 =================
#define QSTR 132
#define VSTR 136
#define ATTN_SMEM ((64 * QSTR + 32 * QSTR + 32 * VSTR + 4 * 16 * 36) * 4)

__global__ __launch_bounds__(128) void attn_kernel(
    const float* __restrict__ Q, const float* __restrict__ Kk,
    const float* __restrict__ V, bf16* __restrict__ Oh, bf16* __restrict__ Ol)
{
    extern __shared__ float smema[];
    float* qs = smema;
    float* ks = qs + 64 * QSTR;
    float* vs = ks + 32 * QSTR;
    float* ps = vs + 32 * VSTR;
    const int qb = blockIdx.x, bh = blockIdx.y;
    const int b = bh >> 4, h = bh & 15;
    const int tid = threadIdx.x, lane = tid & 31, w = tid >> 5;
    const int g = lane >> 2, t = lane & 3;

    const float* Qb = Q + ((size_t)bh * SS + qb * 64) * 128;
    const float* Kb = Kk + (size_t)bh * SS * 128;
    const float* Vb = V + (size_t)bh * SS * 128;

    for (int i = tid; i < 64 * 32; i += 128) {
        int r = i >> 5, c4 = (i & 31) * 4;
        *(float4*)(qs + r * QSTR + c4) = *(const float4*)(Qb + r * 128 + c4);
    }
    __syncthreads();

    float m_[2] = {-1e30f, -1e30f};
    float l_[2] = {0.f, 0.f};
    float o[16][4];
#pragma unroll
    for (int i = 0; i < 16; i++)
#pragma unroll
        for (int c = 0; c < 4; c++) o[i][c] = 0.f;

    const int nkt = qb * 2 + 2;
    const float scale = 0.08838834764831845f;
    float* pw = ps + w * 16 * 36;

    for (int kt = 0; kt < nkt; kt++) {
        for (int i = tid; i < 32 * 32; i += 128) {
            int r = i >> 5, c4 = (i & 31) * 4;
            *(float4*)(ks + r * QSTR + c4) = *(const float4*)(Kb + ((size_t)kt * 32 + r) * 128 + c4);
            *(float4*)(vs + r * VSTR + c4) = *(const float4*)(Vb + ((size_t)kt * 32 + r) * 128 + c4);
        }
        __syncthreads();

        float s[4][4];
#pragma unroll
        for (int nt = 0; nt < 4; nt++)
#pragma unroll
            for (int c = 0; c < 4; c++) s[nt][c] = 0.f;

#pragma unroll
        for (int k8 = 0; k8 < 16; k8++) {
            const int kb2 = k8 * 8;
            uint32_t a[4];
            const int rb = w * 16;
            a[0] = __float_as_uint(qs[(rb + g) * QSTR + kb2 + t]);
            a[1] = __float_as_uint(qs[(rb + g + 8) * QSTR + kb2 + t]);
            a[2] = __float_as_uint(qs[(rb + g) * QSTR + kb2 + t + 4]);
            a[3] = __float_as_uint(qs[(rb + g + 8) * QSTR + kb2 + t + 4]);
#pragma unroll
            for (int nt = 0; nt < 4; nt++) {
                uint32_t b0 = __float_as_uint(ks[(nt * 8 + g) * QSTR + kb2 + t]);
                uint32_t b1 = __float_as_uint(ks[(nt * 8 + g) * QSTR + kb2 + t + 4]);
                mma_tf32(s[nt], a, b0, b1);
            }
        }

        const int qrow0 = qb * 64 + w * 16 + g;
        const int qrow1 = qrow0 + 8;
#pragma unroll
        for (int nt = 0; nt < 4; nt++)
#pragma unroll
            for (int c = 0; c < 4; c++) {
                int row = (c < 2) ? qrow0 : qrow1;
                int kidx = kt * 32 + nt * 8 + 2 * t + (c & 1);
                float v = s[nt][c] * scale;
                if (kidx > row) v = -1e30f;
                s[nt][c] = v;
            }

        float mx0 = -1e30f, mx1 = -1e30f;
#pragma unroll
        for (int nt = 0; nt < 4; nt++) {
            mx0 = fmaxf(mx0, fmaxf(s[nt][0], s[nt][1]));
            mx1 = fmaxf(mx1, fmaxf(s[nt][2], s[nt][3]));
        }
#pragma unroll
        for (int off = 1; off < 4; off <<= 1) {
            mx0 = fmaxf(mx0, __shfl_xor_sync(0xffffffffu, mx0, off));
            mx1 = fmaxf(mx1, __shfl_xor_sync(0xffffffffu, mx1, off));
        }
        float mn0 = fmaxf(m_[0], mx0), mn1 = fmaxf(m_[1], mx1);
        float al0 = expf(m_[0] - mn0), al1 = expf(m_[1] - mn1);
        float rs0 = 0.f, rs1 = 0.f;
#pragma unroll
        for (int nt = 0; nt < 4; nt++) {
            s[nt][0] = expf(s[nt][0] - mn0);
            s[nt][1] = expf(s[nt][1] - mn0);
            s[nt][2] = expf(s[nt][2] - mn1);
            s[nt][3] = expf(s[nt][3] - mn1);
            rs0 += s[nt][0] + s[nt][1];
            rs1 += s[nt][2] + s[nt][3];
        }
#pragma unroll
        for (int off = 1; off < 4; off <<= 1) {
            rs0 += __shfl_xor_sync(0xffffffffu, rs0, off);
            rs1 += __shfl_xor_sync(0xffffffffu, rs1, off);
        }
        l_[0] = l_[0] * al0 + rs0;
        l_[1] = l_[1] * al1 + rs1;
        m_[0] = mn0; m_[1] = mn1;
#pragma unroll
        for (int nt = 0; nt < 16; nt++) {
            o[nt][0] *= al0; o[nt][1] *= al0;
            o[nt][2] *= al1; o[nt][3] *= al1;
        }

#pragma unroll
        for (int nt = 0; nt < 4; nt++) {
            pw[g * 36 + nt * 8 + 2 * t] = rtf(s[nt][0]);
            pw[g * 36 + nt * 8 + 2 * t + 1] = rtf(s[nt][1]);
            pw[(g + 8) * 36 + nt * 8 + 2 * t] = rtf(s[nt][2]);
            pw[(g + 8) * 36 + nt * 8 + 2 * t + 1] = rtf(s[nt][3]);
        }
        __syncwarp();

#pragma unroll
        for (int k8 = 0; k8 < 4; k8++) {
            const int kb2 = k8 * 8;
            uint32_t a[4];
            a[0] = __float_as_uint(pw[g * 36 + kb2 + t]);
            a[1] = __float_as_uint(pw[(g + 8) * 36 + kb2 + t]);
            a[2] = __float_as_uint(pw[g * 36 + kb2 + t + 4]);
            a[3] = __float_as_uint(pw[(g + 8) * 36 + kb2 + t + 4]);
#pragma unroll
            for (int nt = 0; nt < 16; nt++) {
                uint32_t b0 = __float_as_uint(vs[(kb2 + t) * VSTR + nt * 8 + g]);
                uint32_t b1 = __float_as_uint(vs[(kb2 + t + 4) * VSTR + nt * 8 + g]);
                mma_tf32(o[nt], a, b0, b1);
            }
        }
        __syncwarp();
        __syncthreads();
    }

    float inv0 = 1.f / l_[0], inv1 = 1.f / l_[1];
    const size_t gr0 = (size_t)b * SS + qb * 64 + w * 16 + g;
#pragma unroll
    for (int nt = 0; nt < 16; nt++) {
        int col = h * 128 + nt * 8 + 2 * t;
        bf16 h0, l0;
        hilo(o[nt][0] * inv0, h0, l0);
        Oh[gr0 * DD + col] = h0; Ol[gr0 * DD + col] = l0;
        hilo(o[nt][1] * inv0, h0, l0);
        Oh[gr0 * DD + col + 1] = h0; Ol[gr0 * DD + col + 1] = l0;
        hilo(o[nt][2] * inv1, h0, l0);
        Oh[(gr0 + 8) * DD + col] = h0; Ol[(gr0 + 8) * DD + col] = l0;
        hilo(o[nt][3] * inv1, h0, l0);
        Oh[(gr0 + 8) * DD + col + 1] = h0; Ol[(gr0 + 8) * DD + col + 1] = l0;
    }
}

extern "C" void kernel_launch(void* const* d_in, const int* in_sizes, int n_in,
                              void* d_out, int out_size)
{
    (void)in_sizes; (void)n_in; (void)out_size;
    const float* x    = (const float*)d_in[0];
    const float* anw  = (const float*)d_in[1];
    const float* anb  = (const float*)d_in[2];
    const float* Wdq  = (const float*)d_in[3];
    const float* qlw  = (const float*)d_in[4];
    const float* qlb  = (const float*)d_in[5];
    const float* Wuq  = (const float*)d_in[6];
    const float* Wdkv = (const float*)d_in[7];
    const float* klw  = (const float*)d_in[8];
    const float* klb  = (const float*)d_in[9];
    const float* Wukv = (const float*)d_in[10];
    const float* Wo   = (const float*)d_in[11];
    const float* fnw  = (const float*)d_in[12];
    const float* fnb  = (const float*)d_in[13];
    const float* W1   = (const float*)d_in[14];
    const float* b1   = (const float*)d_in[15];
    const float* W2   = (const float*)d_in[16];
    const float* b2   = (const float*)d_in[17];

    float* out = (float*)d_out;
    float* ckv = out + (size_t)MMr * DD;

    float *pcq, *pqraw, *pkvraw, *pq, *pk, *pv, *px2;
    bf16 *phh, *phl, *pcqh, *pcql, *pkvlh, *pkvll, *poh, *pol, *pff1h, *pff1l;
    bf16 *pdqTh, *pdqTl, *pdkvTh, *pdkvTl, *puqTh, *puqTl, *pukvTh, *pukvTl;
    bf16 *pw1Th, *pw1Tl, *pw2Th, *pw2Tl, *pwoCh, *pwoCl;

    cudaGetSymbolAddress((void**)&pcq, g_cq);
    cudaGetSymbolAddress((void**)&pqraw, g_qraw);
    cudaGetSymbolAddress((void**)&pkvraw, g_kvraw);
    cudaGetSymbolAddress((void**)&pq, g_q);
    cudaGetSymbolAddress((void**)&pk, g_k);
    cudaGetSymbolAddress((void**)&pv, g_v);
    cudaGetSymbolAddress((void**)&px2, g_x2);
    cudaGetSymbolAddress((void**)&phh, g_hh);
    cudaGetSymbolAddress((void**)&phl, g_hl);
    cudaGetSymbolAddress((void**)&pcqh, g_cqh);
    cudaGetSymbolAddress((void**)&pcql, g_cql);
    cudaGetSymbolAddress((void**)&pkvlh, g_kvlh);
    cudaGetSymbolAddress((void**)&pkvll, g_kvll);
    cudaGetSymbolAddress((void**)&poh, g_oh);
    cudaGetSymbolAddress((void**)&pol, g_ol);
    cudaGetSymbolAddress((void**)&pff1h, g_ff1h);
    cudaGetSymbolAddress((void**)&pff1l, g_ff1l);
    cudaGetSymbolAddress((void**)&pdqTh, g_dqTh);
    cudaGetSymbolAddress((void**)&pdqTl, g_dqTl);
    cudaGetSymbolAddress((void**)&pdkvTh, g_dkvTh);
    cudaGetSymbolAddress((void**)&pdkvTl, g_dkvTl);
    cudaGetSymbolAddress((void**)&puqTh, g_uqTh);
    cudaGetSymbolAddress((void**)&puqTl, g_uqTl);
    cudaGetSymbolAddress((void**)&pukvTh, g_ukvTh);
    cudaGetSymbolAddress((void**)&pukvTl, g_ukvTl);
    cudaGetSymbolAddress((void**)&pw1Th, g_w1Th);
    cudaGetSymbolAddress((void**)&pw1Tl, g_w1Tl);
    cudaGetSymbolAddress((void**)&pw2Th, g_w2Th);
    cudaGetSymbolAddress((void**)&pw2Tl, g_w2Tl);
    cudaGetSymbolAddress((void**)&pwoCh, g_woCh);
    cudaGetSymbolAddress((void**)&pwoCl, g_woCl);

    cudaFuncSetAttribute(gemm_bf<0>, cudaFuncAttributeMaxDynamicSharedMemorySize, GEMM2_SMEM);
    cudaFuncSetAttribute(gemm_bf<1>, cudaFuncAttributeMaxDynamicSharedMemorySize, GEMM2_SMEM);
    cudaFuncSetAttribute(gemm_bf<2>, cudaFuncAttributeMaxDynamicSharedMemorySize, GEMM2_SMEM);
    cudaFuncSetAttribute(attn_kernel, cudaFuncAttributeMaxDynamicSharedMemorySize, ATTN_SMEM);

    dim3 t32x8(32, 8);
    freqs_kernel<<<1, 32>>>();
    // weight conversions (one pass; captured in graph each replay, ~60us)
    tconv_kernel<<<dim3(64, 32), t32x8>>>(Wdq, DD, QPd, DD, pdqTh, pdqTl);
    tconv_kernel<<<dim3(64, 48), t32x8>>>(Wdkv, DD, CKVN, DD, pdkvTh, pdkvTl);
    tconv_kernel<<<dim3(32, 64), t32x8>>>(Wuq, QPd, DD, QPd, puqTh, puqTl);
    tconv_kernel<<<dim3(44, 96), t32x8>>>(Wukv, KVPd, 3072, KVL_PAD, pukvTh, pukvTl);
    tconv_kernel<<<dim3(64, 256), t32x8>>>(W1, DD, FFd, DD, pw1Th, pw1Tl);
    tconv_kernel<<<dim3(256, 64), t32x8>>>(W2, FFd, DD, FFd, pw2Th, pw2Tl);
    wocv_kernel<<<(DD * DD + 255) / 256, 256>>>(Wo, pwoCh, pwoCl);

    // h = LN(x) -> hi/lo
    ln2_kernel<<<MMr, 256, DD * 4>>>(x, DD, DD, anw, anb, phh, phl, DD, DD);
    // cq_raw = h @ W_dq
    gemm_bf<0><<<dim3(QPd / BN2, MMr / BM2), 256, GEMM2_SMEM>>>(
        phh, phl, DD, pdqTh, pdqTl, DD, pcq, nullptr, nullptr, QPd, QPd, DD / 64, nullptr, nullptr, 0);
    // ckv = h @ W_dkv  (N=1429 guarded, Npad grid 1536)
    gemm_bf<0><<<dim3(DKV_NPAD / BN2, MMr / BM2), 256, GEMM2_SMEM>>>(
        phh, phl, DD, pdkvTh, pdkvTl, DD, ckv, nullptr, nullptr, CKVN, CKVN, DD / 64, nullptr, nullptr, 0);
    ln2_kernel<<<MMr, 256, QPd * 4>>>(pcq, QPd, QPd, qlw, qlb, pcqh, pcql, QPd, QPd);
    ln2_kernel<<<MMr, 256, KVPd * 4>>>(ckv, CKVN, KVPd, klw, klb, pkvlh, pkvll, KVL_PAD, KVL_PAD);
    // Q_raw = cq @ W_uq
    gemm_bf<0><<<dim3(DD / BN2, MMr / BM2), 256, GEMM2_SMEM>>>(
        pcqh, pcql, QPd, puqTh, puqTl, QPd, pqraw, nullptr, nullptr, DD, DD, QPd / 64, nullptr, nullptr, 0);
    // KV_raw = kv_lora @ W_ukv
    gemm_bf<0><<<dim3(3072 / BN2, MMr / BM2), 256, GEMM2_SMEM>>>(
        pkvlh, pkvll, KVL_PAD, pukvTh, pukvTl, KVL_PAD, pkvraw, nullptr, nullptr, 3072, 3072, KVL_PAD / 64,
        nullptr, nullptr, 0);

    rope_q_kernel<<<MMr, 256>>>(pqraw, pq);
    reorder_kv_kernel<<<MMr, 256>>>(pkvraw, ckv, pk, pv);
    attn_kernel<<<dim3(SS / 64, BB * HH), 128, ATTN_SMEM>>>(pq, pk, pv, poh, pol);

    // x2 = x + o @ Wo^T
    gemm_bf<2><<<dim3(DD / BN2, MMr / BM2), 256, GEMM2_SMEM>>>(
        poh, pol, DD, pwoCh, pwoCl, DD, px2, nullptr, nullptr, DD, DD, DD / 64, nullptr, x, DD);
    ln2_kernel<<<MMr, 256, DD * 4>>>(px2, DD, DD, fnw, fnb, phh, phl, DD, DD);
    // ff1 = gelu(h @ W1 + b1) -> hi/lo
    gemm_bf<1><<<dim3(FFd / BN2, MMr / BM2), 256, GEMM2_SMEM>>>(
        phh, phl, DD, pw1Th, pw1Tl, DD, nullptr, pff1h, pff1l, FFd, FFd, DD / 64, b1, nullptr, 0);
    // out = x2 + ff1 @ W2 + b2
    gemm_bf<2><<<dim3(DD / BN2, MMr / BM2), 256, GEMM2_SMEM>>>(
        pff1h, pff1l, FFd, pw2Th, pw2Tl, FFd, out, nullptr, nullptr, DD, DD, FFd / 64, b2, px2, DD);
}

// round 12
// speedup vs baseline: 1.7256x; 1.7256x over previous
#include <cuda_runtime.h>
#include <cuda_bf16.h>
#include <cuda_fp16.h>
#include <math.h>
#include <stdint.h>

#define BB 2
#define SS 2048
#define DD 2048
#define HH 16
#define QPd 1024
#define KVPd 1365
#define CKVN 1429
#define FFd 8192
#define MMr 4096
#define KVL_PAD 1376
#define WDKV_PAD 1440

__device__ float g_h[(size_t)MMr * DD];
__device__ float g_cq[(size_t)MMr * QPd];
__device__ float g_qraw[(size_t)MMr * DD];
__device__ float g_kvlora[(size_t)MMr * KVL_PAD];
__device__ float g_kvraw[(size_t)MMr * 3072];
__device__ float g_q[(size_t)MMr * DD];
__device__ float g_k[(size_t)MMr * DD];
__device__ float g_v[(size_t)MMr * DD];
__device__ float g_o[(size_t)MMr * DD];
__device__ float g_x2[(size_t)MMr * DD];
__device__ float g_woT[(size_t)DD * DD];
__device__ float g_wdkvp[(size_t)DD * WDKV_PAD];
__device__ float g_wdqc[(size_t)DD * QPd];
__device__ float g_wuqc[(size_t)QPd * DD];
__device__ float g_wukvc[(size_t)KVPd * 3072];
__device__ float g_freqs[32];
// f16 path (FF GEMMs)
__device__ __half g_w1t[(size_t)FFd * DD];   // W1^T [N=FF][K=D]
__device__ __half g_w2t[(size_t)DD * FFd];   // W2^T [N=D][K=FF]
__device__ __half g_hf[(size_t)MMr * DD];    // LN(x2) as f16
__device__ __half g_ff1f[(size_t)MMr * FFd]; // gelu out as f16

__device__ __forceinline__ uint32_t f2tf(float x) {
    uint32_t u;
    asm("cvt.rna.tf32.f32 %0, %1;" : "=r"(u) : "f"(x));
    return u;
}
__device__ __forceinline__ float rtf(float x) { return __uint_as_float(f2tf(x)); }

__device__ __forceinline__ void mma_tf32(float* c, const uint32_t* a, uint32_t b0, uint32_t b1) {
    asm volatile(
        "mma.sync.aligned.m16n8k8.row.col.f32.tf32.tf32.f32 "
        "{%0,%1,%2,%3}, {%4,%5,%6,%7}, {%8,%9}, {%0,%1,%2,%3};"
        : "+f"(c[0]), "+f"(c[1]), "+f"(c[2]), "+f"(c[3])
        : "r"(a[0]), "r"(a[1]), "r"(a[2]), "r"(a[3]), "r"(b0), "r"(b1));
}
__device__ __forceinline__ void mma_h(uint32_t& d0, uint32_t& d1, const uint32_t* a,
                                      uint32_t b0, uint32_t b1, uint32_t c0, uint32_t c1) {
    asm volatile(
        "mma.sync.aligned.m16n8k16.row.col.f16.f16.f16.f16 "
        "{%0,%1}, {%2,%3,%4,%5}, {%6,%7}, {%8,%9};"
        : "=r"(d0), "=r"(d1)
        : "r"(a[0]), "r"(a[1]), "r"(a[2]), "r"(a[3]), "r"(b0), "r"(b1), "r"(c0), "r"(c1));
}
__device__ __forceinline__ void cp16(void* dst, const void* src) {
    uint32_t d = (uint32_t)__cvta_generic_to_shared(dst);
    asm volatile("cp.async.cg.shared.global [%0], [%1], 16;" :: "r"(d), "l"(src));
}
__device__ __forceinline__ void cp16p(float* dst, const float* src, const float* safe, bool p) {
    uint32_t d = (uint32_t)__cvta_generic_to_shared(dst);
    const float* s = p ? src : safe;
    int sz = p ? 16 : 0;
    asm volatile("cp.async.cg.shared.global [%0], [%1], 16, %2;" :: "r"(d), "l"(s), "r"(sz));
}

// ================= tf32 GEMM (unchanged from R8 best) =================
#define BM 128
#define BN 128
#define BKt 32
#define ASTR 36
#define BSTR 136
#define AS_ELE (BM * ASTR)
#define BS_ELE (BKt * BSTR)
#define GEMM_SMEM (2 * (AS_ELE + BS_ELE) * 4)

// EPI: 0 none, 2 (+bias)+residual
template <int EPI>
__global__ __launch_bounds__(256) void gemm_kernel(
    const float* __restrict__ A, int lda, int kbuf,
    const float* __restrict__ B, int ldb, int nbuf,
    float* __restrict__ C, int ldc, int M, int N, int K,
    const float* __restrict__ bias, const float* __restrict__ res, int ldres)
{
    extern __shared__ float smemb[];
    float* As = smemb;
    float* Bs = smemb + 2 * AS_ELE;
    const int tid = threadIdx.x, lane = tid & 31, warp = tid >> 5;
    const int wm = warp >> 1, wn = warp & 1;
    const int bm0 = blockIdx.y * BM, bn0 = blockIdx.x * BN;

    float acc[2][8][4];
#pragma unroll
    for (int i = 0; i < 2; i++)
#pragma unroll
        for (int j = 0; j < 8; j++)
#pragma unroll
            for (int c = 0; c < 4; c++) acc[i][j][c] = 0.f;

    const int KT = (K + BKt - 1) / BKt;
    auto load_tiles = [&](int buf, int k0) {
        float* Ab = As + buf * AS_ELE;
        float* Bb = Bs + buf * BS_ELE;
        const int ar = tid >> 3, ac = (tid & 7) * 4;
#pragma unroll
        for (int i = 0; i < 4; i++) {
            int r = i * 32 + ar;
            cp16p(Ab + r * ASTR + ac, A + (size_t)(bm0 + r) * lda + k0 + ac, A, (k0 + ac) < kbuf);
        }
        const int br = tid >> 5, bc = (tid & 31) * 4;
#pragma unroll
        for (int i = 0; i < 4; i++) {
            int r = i * 8 + br;
            cp16p(Bb + r * BSTR + bc, B + (size_t)(k0 + r) * ldb + bn0 + bc, B,
                  ((k0 + r) < K) && ((bn0 + bc) < nbuf));
        }
        asm volatile("cp.async.commit_group;");
    };

    load_tiles(0, 0);
    int buf = 0;
    for (int kt = 0; kt < KT; kt++) {
        if (kt + 1 < KT) {
            load_tiles(buf ^ 1, (kt + 1) * BKt);
            asm volatile("cp.async.wait_group 1;");
        } else {
            asm volatile("cp.async.wait_group 0;");
        }
        __syncthreads();
        const float* Ab = As + buf * AS_ELE;
        const float* Bb = Bs + buf * BS_ELE;
#pragma unroll
        for (int ks = 0; ks < BKt / 8; ks++) {
            const int kb = ks * 8;
            uint32_t a[2][4];
#pragma unroll
            for (int im = 0; im < 2; im++) {
                const int r = wm * 32 + im * 16 + (lane >> 2);
                const int cc = kb + (lane & 3);
                a[im][0] = __float_as_uint(Ab[r * ASTR + cc]);
                a[im][1] = __float_as_uint(Ab[(r + 8) * ASTR + cc]);
                a[im][2] = __float_as_uint(Ab[r * ASTR + cc + 4]);
                a[im][3] = __float_as_uint(Ab[(r + 8) * ASTR + cc + 4]);
            }
#pragma unroll
            for (int in_ = 0; in_ < 8; in_++) {
                const int c = wn * 64 + in_ * 8 + (lane >> 2);
                uint32_t b0 = __float_as_uint(Bb[(kb + (lane & 3)) * BSTR + c]);
                uint32_t b1 = __float_as_uint(Bb[(kb + (lane & 3) + 4) * BSTR + c]);
#pragma unroll
                for (int im = 0; im < 2; im++) mma_tf32(acc[im][in_], a[im], b0, b1);
            }
        }
        __syncthreads();
        buf ^= 1;
    }
#pragma unroll
    for (int im = 0; im < 2; im++)
#pragma unroll
        for (int in_ = 0; in_ < 8; in_++) {
            const int r0 = bm0 + wm * 32 + im * 16 + (lane >> 2);
            const int c0 = bn0 + wn * 64 + in_ * 8 + 2 * (lane & 3);
#pragma unroll
            for (int cc = 0; cc < 4; cc++) {
                int r = r0 + (cc >> 1) * 8;
                int c = c0 + (cc & 1);
                if (c < N) {
                    float v = acc[im][in_][cc];
                    if (EPI == 2) {
                        if (bias) v += bias[c];
                        v += res[(size_t)r * ldres + c];
                    }
                    C[(size_t)r * ldc + c] = v;
                }
            }
        }
}

// ================= f16 GEMM probe (FF layers) =================
// A [M,K] f16, B [N,K] f16 (K-contig). f16 accumulate chained over K=32, promoted to fp32.
#define HSTR 40
#define HT_ELE (128 * HSTR)
#define GEMMH_SMEM (4 * HT_ELE * 2)  // 2 tiles x 2 buffers x 2B

// EPI: 1 bias+GELU -> f16 out ; 2 bias+residual -> fp32 out
template <int EPI>
__global__ __launch_bounds__(256) void gemm_h(
    const __half* __restrict__ A, int lda,
    const __half* __restrict__ B, int ldb,
    float* __restrict__ C, __half* __restrict__ Ch, int ldc,
    int N, int K,
    const float* __restrict__ bias, const float* __restrict__ res, int ldres)
{
    extern __shared__ __half smh[];
    __half* As = smh;                  // [2][128][40]
    __half* Bs = smh + 2 * HT_ELE;     // [2][128][40]
    const int tid = threadIdx.x, lane = tid & 31, warp = tid >> 5;
    const int wm = warp >> 1, wn = warp & 1;
    const int bm0 = blockIdx.y * 128, bn0 = blockIdx.x * 128;
    const int g = lane >> 2, t = lane & 3;

    float acc[2][8][4];
#pragma unroll
    for (int i = 0; i < 2; i++)
#pragma unroll
        for (int j = 0; j < 8; j++)
#pragma unroll
            for (int c = 0; c < 4; c++) acc[i][j][c] = 0.f;

    const int KT = K / 32;
    auto load_tiles = [&](int buf, int k0) {
        __half* Ab = As + buf * HT_ELE;
        __half* Bb = Bs + buf * HT_ELE;
#pragma unroll
        for (int i = 0; i < 2; i++) {
            int idx = i * 256 + tid;
            int r = idx >> 2, s = idx & 3;
            cp16(Ab + r * HSTR + s * 8, A + (size_t)(bm0 + r) * lda + k0 + s * 8);
        }
#pragma unroll
        for (int i = 0; i < 2; i++) {
            int idx = i * 256 + tid;
            int r = idx >> 2, s = idx & 3;
            cp16(Bb + r * HSTR + s * 8, B + (size_t)(bn0 + r) * ldb + k0 + s * 8);
        }
        asm volatile("cp.async.commit_group;");
    };

    load_tiles(0, 0);
    int buf = 0;
    for (int kt = 0; kt < KT; kt++) {
        if (kt + 1 < KT) {
            load_tiles(buf ^ 1, (kt + 1) * 32);
            asm volatile("cp.async.wait_group 1;");
        } else {
            asm volatile("cp.async.wait_group 0;");
        }
        __syncthreads();
        const __half* Ab = As + buf * HT_ELE;
        const __half* Bb = Bs + buf * HT_ELE;

        uint32_t af[2][2][4];  // [kstep][im][frag]
#pragma unroll
        for (int ks = 0; ks < 2; ks++) {
            const int kb = ks * 16 + 2 * t;
#pragma unroll
            for (int im = 0; im < 2; im++) {
                const int r = wm * 32 + im * 16 + g;
                af[ks][im][0] = *(const uint32_t*)(Ab + r * HSTR + kb);
                af[ks][im][1] = *(const uint32_t*)(Ab + (r + 8) * HSTR + kb);
                af[ks][im][2] = *(const uint32_t*)(Ab + r * HSTR + kb + 8);
                af[ks][im][3] = *(const uint32_t*)(Ab + (r + 8) * HSTR + kb + 8);
            }
        }
#pragma unroll
        for (int nt = 0; nt < 8; nt++) {
            const int c = wn * 64 + nt * 8 + g;
            uint32_t b00 = *(const uint32_t*)(Bb + c * HSTR + 2 * t);
            uint32_t b01 = *(const uint32_t*)(Bb + c * HSTR + 2 * t + 8);
            uint32_t b10 = *(const uint32_t*)(Bb + c * HSTR + 16 + 2 * t);
            uint32_t b11 = *(const uint32_t*)(Bb + c * HSTR + 16 + 2 * t + 8);
#pragma unroll
            for (int im = 0; im < 2; im++) {
                uint32_t d0, d1, e0, e1;
                mma_h(d0, d1, af[0][im], b00, b01, 0u, 0u);
                mma_h(e0, e1, af[1][im], b10, b11, d0, d1);
                float2 p0 = __half22float2(*reinterpret_cast<__half2*>(&e0));
                float2 p1 = __half22float2(*reinterpret_cast<__half2*>(&e1));
                acc[im][nt][0] += p0.x;
                acc[im][nt][1] += p0.y;
                acc[im][nt][2] += p1.x;
                acc[im][nt][3] += p1.y;
            }
        }
        __syncthreads();
        buf ^= 1;
    }
#pragma unroll
    for (int im = 0; im < 2; im++)
#pragma unroll
        for (int nt = 0; nt < 8; nt++) {
            const int r0 = bm0 + wm * 32 + im * 16 + g;
            const int c0 = bn0 + wn * 64 + nt * 8 + 2 * t;
#pragma unroll
            for (int e = 0; e < 4; e++) {
                int r = r0 + (e >> 1) * 8;
                int c = c0 + (e & 1);
                float v = acc[im][nt][e];
                if (EPI == 1) {
                    v += bias[c];
                    v = 0.5f * v * (1.f + erff(v * 0.7071067811865475f));
                    Ch[(size_t)r * ldc + c] = __float2half_rn(v);
                } else {
                    v += bias[c];
                    v += res[(size_t)r * ldres + c];
                    C[(size_t)r * ldc + c] = v;
                }
            }
        }
}

// ================= LayerNorm variants =================
__global__ void ln_kernel(const float* __restrict__ in, int ldin, int cols,
                          const float* __restrict__ w, const float* __restrict__ b,
                          float* __restrict__ out, int ldout, int padto)
{
    extern __shared__ float sbuf[];
    __shared__ float red[8];
    __shared__ float bc[2];
    const int row = blockIdx.x, tid = threadIdx.x, lane = tid & 31, warp = tid >> 5;
    const float* ip = in + (size_t)row * ldin;
    float s = 0.f;
    for (int c = tid; c < cols; c += 256) { float v = ip[c]; sbuf[c] = v; s += v; }
#pragma unroll
    for (int o = 16; o > 0; o >>= 1) s += __shfl_xor_sync(0xffffffffu, s, o);
    if (lane == 0) red[warp] = s;
    __syncthreads();
    if (tid == 0) { float t = 0; for (int i = 0; i < 8; i++) t += red[i]; bc[0] = t / cols; }
    __syncthreads();
    float mean = bc[0], vs = 0.f;
    for (int c = tid; c < cols; c += 256) { float d = sbuf[c] - mean; vs += d * d; }
#pragma unroll
    for (int o = 16; o > 0; o >>= 1) vs += __shfl_xor_sync(0xffffffffu, vs, o);
    if (lane == 0) red[warp] = vs;
    __syncthreads();
    if (tid == 0) { float t = 0; for (int i = 0; i < 8; i++) t += red[i]; bc[1] = rsqrtf(t / cols + 1e-5f); }
    __syncthreads();
    float inv = bc[1];
    float* op = out + (size_t)row * ldout;
    for (int c = tid; c < cols; c += 256) op[c] = rtf((sbuf[c] - mean) * inv * w[c] + b[c]);
    for (int c = cols + tid; c < padto; c += 256) op[c] = 0.f;
}

__global__ void ln_h_kernel(const float* __restrict__ in, int cols,
                            const float* __restrict__ w, const float* __restrict__ b,
                            __half* __restrict__ out)
{
    extern __shared__ float sbuf[];
    __shared__ float red[8];
    __shared__ float bc[2];
    const int row = blockIdx.x, tid = threadIdx.x, lane = tid & 31, warp = tid >> 5;
    const float* ip = in + (size_t)row * cols;
    float s = 0.f;
    for (int c = tid; c < cols; c += 256) { float v = ip[c]; sbuf[c] = v; s += v; }
#pragma unroll
    for (int o = 16; o > 0; o >>= 1) s += __shfl_xor_sync(0xffffffffu, s, o);
    if (lane == 0) red[warp] = s;
    __syncthreads();
    if (tid == 0) { float t = 0; for (int i = 0; i < 8; i++) t += red[i]; bc[0] = t / cols; }
    __syncthreads();
    float mean = bc[0], vs = 0.f;
    for (int c = tid; c < cols; c += 256) { float d = sbuf[c] - mean; vs += d * d; }
#pragma unroll
    for (int o = 16; o > 0; o >>= 1) vs += __shfl_xor_sync(0xffffffffu, vs, o);
    if (lane == 0) red[warp] = vs;
    __syncthreads();
    if (tid == 0) { float t = 0; for (int i = 0; i < 8; i++) t += red[i]; bc[1] = rsqrtf(t / cols + 1e-5f); }
    __syncthreads();
    float inv = bc[1];
    __half* op = out + (size_t)row * cols;
    for (int c = tid; c < cols; c += 256) op[c] = __float2half_rn((sbuf[c] - mean) * inv * w[c] + b[c]);
}

__global__ void freqs_kernel() {
    int j = threadIdx.x;
    if (j < 32) g_freqs[j] = (float)exp(-(double)j * 0.14391156831212787);
}

__global__ void transpose_kernel(const float* __restrict__ in, float* __restrict__ out, int n) {
    __shared__ float t[32][33];
    int x = blockIdx.x * 32 + threadIdx.x;
    int y = blockIdx.y * 32 + threadIdx.y;
#pragma unroll
    for (int i = 0; i < 32; i += 8) t[threadIdx.y + i][threadIdx.x] = in[(size_t)(y + i) * n + x];
    __syncthreads();
    int ox = blockIdx.y * 32 + threadIdx.x;
    int oy = blockIdx.x * 32 + threadIdx.y;
#pragma unroll
    for (int i = 0; i < 32; i += 8) out[(size_t)(oy + i) * n + ox] = rtf(t[threadIdx.x][threadIdx.y + i]);
}

// [K,N] fp32 -> [N,K] f16 transpose-convert (dims multiples of 32)
__global__ void tconv_h_kernel(const float* __restrict__ in, int K, int N, __half* __restrict__ out) {
    __shared__ float tb[32][33];
    const int k0 = blockIdx.x * 32, n0 = blockIdx.y * 32;
    const int tx = threadIdx.x, ty = threadIdx.y;
#pragma unroll
    for (int i = 0; i < 32; i += 8) tb[ty + i][tx] = in[(size_t)(k0 + ty + i) * N + n0 + tx];
    __syncthreads();
#pragma unroll
    for (int i = 0; i < 32; i += 8)
        out[(size_t)(n0 + ty + i) * K + k0 + tx] = __float2half_rn(tb[tx][ty + i]);
}

__global__ void pad_wdkv_kernel(const float* __restrict__ in, float* __restrict__ out) {
    int r = blockIdx.x;
    for (int c = threadIdx.x; c < WDKV_PAD; c += 256)
        out[(size_t)r * WDKV_PAD + c] = (c < CKVN) ? rtf(in[(size_t)r * CKVN + c]) : 0.f;
}

#define NW0 ((size_t)DD * QPd)
#define NW1 ((size_t)QPd * DD)
#define NW2 ((size_t)KVPd * 3072)
__global__ void cvtw_kernel(const float* __restrict__ s0, float* __restrict__ d0,
                            const float* __restrict__ s1, float* __restrict__ d1,
                            const float* __restrict__ s2, float* __restrict__ d2)
{
    const size_t total = NW0 + NW1 + NW2;
    for (size_t i = (size_t)blockIdx.x * blockDim.x + threadIdx.x; i < total;
         i += (size_t)gridDim.x * blockDim.x) {
        size_t j = i;
        if (j < NW0) { d0[j] = rtf(s0[j]); continue; }
        j -= NW0;
        if (j < NW1) { d1[j] = rtf(s1[j]); continue; }
        j -= NW1;
        d2[j] = rtf(s2[j]);
    }
}

__global__ void rope_q_kernel(const float* __restrict__ qraw, float* __restrict__ qout) {
    int bs = blockIdx.x;
    int s = bs & (SS - 1), b = bs >> 11;
    for (int i = threadIdx.x; i < DD; i += 256) {
        int hh = i >> 7, d = i & 127;
        const float* src = qraw + (size_t)bs * DD + hh * 128;
        float v;
        if (d < 64) {
            v = src[d];
        } else {
            int dd = d - 64;
            int j = dd & 31;
            float t = (float)s * g_freqs[j];
            float x = src[64 + dd];
            float rx = (dd < 32) ? -src[64 + dd + 32] : src[64 + dd - 32];
            v = x * cosf(t) + rx * sinf(t);
        }
        qout[(((size_t)b * HH + hh) * SS + s) * 128 + d] = rtf(v);
    }
}

__global__ void reorder_kv_kernel(const float* __restrict__ kvraw, const float* __restrict__ ckv,
                                  float* __restrict__ kout, float* __restrict__ vout) {
    __shared__ float kr[64];
    int bs = blockIdx.x;
    int s = bs & (SS - 1), b = bs >> 11;
    int tid = threadIdx.x;
    if (tid < 64) {
        int dd = tid, j = dd & 31;
        float t = (float)s * g_freqs[j];
        const float* src = ckv + (size_t)bs * CKVN + KVPd;
        float x = src[dd];
        float rx = (dd < 32) ? -src[dd + 32] : src[dd - 32];
        kr[dd] = rtf(x * cosf(t) + rx * sinf(t));
    }
    __syncthreads();
    for (int i = tid; i < HH * 192; i += 256) {
        int hh = i / 192, d = i % 192;
        float v = rtf(kvraw[(size_t)bs * 3072 + i]);
        size_t base = (((size_t)b * HH + hh) * SS + s) * 128;
        if (d < 64) kout[base + d] = v;
        else vout[base + (d - 64)] = v;
    }
    for (int i = tid; i < HH * 64; i += 256) {
        int hh = i >> 6, dd = i & 63;
        kout[(((size_t)b * HH + hh) * SS + s) * 128 + 64 + dd] = kr[dd];
    }
}

// ================= attention (tf32, unchanged from R8) =================
#define QSTR 132
#define VSTR 136
#define ATTN_SMEM ((64 * QSTR + 32 * QSTR + 32 * VSTR + 4 * 16 * 36) * 4)

__global__ __launch_bounds__(128) void attn_kernel(
    const float* __restrict__ Q, const float* __restrict__ Kk,
    const float* __restrict__ V, float* __restrict__ O)
{
    extern __shared__ float smema[];
    float* qs = smema;
    float* ks = qs + 64 * QSTR;
    float* vs = ks + 32 * QSTR;
    float* ps = vs + 32 * VSTR;
    const int qb = blockIdx.x, bh = blockIdx.y;
    const int b = bh >> 4, h = bh & 15;
    const int tid = threadIdx.x, lane = tid & 31, w = tid >> 5;
    const int g = lane >> 2, t = lane & 3;

    const float* Qb = Q + ((size_t)bh * SS + qb * 64) * 128;
    const float* Kb = Kk + (size_t)bh * SS * 128;
    const float* Vb = V + (size_t)bh * SS * 128;

    for (int i = tid; i < 64 * 32; i += 128) {
        int r = i >> 5, c4 = (i & 31) * 4;
        *(float4*)(qs + r * QSTR + c4) = *(const float4*)(Qb + r * 128 + c4);
    }
    __syncthreads();

    float m_[2] = {-1e30f, -1e30f};
    float l_[2] = {0.f, 0.f};
    float o[16][4];
#pragma unroll
    for (int i = 0; i < 16; i++)
#pragma unroll
        for (int c = 0; c < 4; c++) o[i][c] = 0.f;

    const int nkt = qb * 2 + 2;
    const float scale = 0.08838834764831845f;
    float* pw = ps + w * 16 * 36;

    for (int kt = 0; kt < nkt; kt++) {
        for (int i = tid; i < 32 * 32; i += 128) {
            int r = i >> 5, c4 = (i & 31) * 4;
            *(float4*)(ks + r * QSTR + c4) = *(const float4*)(Kb + ((size_t)kt * 32 + r) * 128 + c4);
            *(float4*)(vs + r * VSTR + c4) = *(const float4*)(Vb + ((size_t)kt * 32 + r) * 128 + c4);
        }
        __syncthreads();

        float s[4][4];
#pragma unroll
        for (int nt = 0; nt < 4; nt++)
#pragma unroll
            for (int c = 0; c < 4; c++) s[nt][c] = 0.f;

#pragma unroll
        for (int k8 = 0; k8 < 16; k8++) {
            const int kb2 = k8 * 8;
            uint32_t a[4];
            const int rb = w * 16;
            a[0] = __float_as_uint(qs[(rb + g) * QSTR + kb2 + t]);
            a[1] = __float_as_uint(qs[(rb + g + 8) * QSTR + kb2 + t]);
            a[2] = __float_as_uint(qs[(rb + g) * QSTR + kb2 + t + 4]);
            a[3] = __float_as_uint(qs[(rb + g + 8) * QSTR + kb2 + t + 4]);
#pragma unroll
            for (int nt = 0; nt < 4; nt++) {
                uint32_t b0 = __float_as_uint(ks[(nt * 8 + g) * QSTR + kb2 + t]);
                uint32_t b1 = __float_as_uint(ks[(nt * 8 + g) * QSTR + kb2 + t + 4]);
                mma_tf32(s[nt], a, b0, b1);
            }
        }

        const int qrow0 = qb * 64 + w * 16 + g;
        const int qrow1 = qrow0 + 8;
#pragma unroll
        for (int nt = 0; nt < 4; nt++)
#pragma unroll
            for (int c = 0; c < 4; c++) {
                int row = (c < 2) ? qrow0 : qrow1;
                int kidx = kt * 32 + nt * 8 + 2 * t + (c & 1);
                float v = s[nt][c] * scale;
                if (kidx > row) v = -1e30f;
                s[nt][c] = v;
            }

        float mx0 = -1e30f, mx1 = -1e30f;
#pragma unroll
        for (int nt = 0; nt < 4; nt++) {
            mx0 = fmaxf(mx0, fmaxf(s[nt][0], s[nt][1]));
            mx1 = fmaxf(mx1, fmaxf(s[nt][2], s[nt][3]));
        }
#pragma unroll
        for (int off = 1; off < 4; off <<= 1) {
            mx0 = fmaxf(mx0, __shfl_xor_sync(0xffffffffu, mx0, off));
            mx1 = fmaxf(mx1, __shfl_xor_sync(0xffffffffu, mx1, off));
        }
        float mn0 = fmaxf(m_[0], mx0), mn1 = fmaxf(m_[1], mx1);
        float al0 = expf(m_[0] - mn0), al1 = expf(m_[1] - mn1);
        float rs0 = 0.f, rs1 = 0.f;
#pragma unroll
        for (int nt = 0; nt < 4; nt++) {
            s[nt][0] = expf(s[nt][0] - mn0);
            s[nt][1] = expf(s[nt][1] - mn0);
            s[nt][2] = expf(s[nt][2] - mn1);
            s[nt][3] = expf(s[nt][3] - mn1);
            rs0 += s[nt][0] + s[nt][1];
            rs1 += s[nt][2] + s[nt][3];
        }
#pragma unroll
        for (int off = 1; off < 4; off <<= 1) {
            rs0 += __shfl_xor_sync(0xffffffffu, rs0, off);
            rs1 += __shfl_xor_sync(0xffffffffu, rs1, off);
        }
        l_[0] = l_[0] * al0 + rs0;
        l_[1] = l_[1] * al1 + rs1;
        m_[0] = mn0; m_[1] = mn1;
#pragma unroll
        for (int nt = 0; nt < 16; nt++) {
            o[nt][0] *= al0; o[nt][1] *= al0;
            o[nt][2] *= al1; o[nt][3] *= al1;
        }

#pragma unroll
        for (int nt = 0; nt < 4; nt++) {
            pw[g * 36 + nt * 8 + 2 * t] = rtf(s[nt][0]);
            pw[g * 36 + nt * 8 + 2 * t + 1] = rtf(s[nt][1]);
            pw[(g + 8) * 36 + nt * 8 + 2 * t] = rtf(s[nt][2]);
            pw[(g + 8) * 36 + nt * 8 + 2 * t + 1] = rtf(s[nt][3]);
        }
        __syncwarp();

#pragma unroll
        for (int k8 = 0; k8 < 4; k8++) {
            const int kb2 = k8 * 8;
            uint32_t a[4];
            a[0] = __float_as_uint(pw[g * 36 + kb2 + t]);
            a[1] = __float_as_uint(pw[(g + 8) * 36 + kb2 + t]);
            a[2] = __float_as_uint(pw[g * 36 + kb2 + t + 4]);
            a[3] = __float_as_uint(pw[(g + 8) * 36 + kb2 + t + 4]);
#pragma unroll
            for (int nt = 0; nt < 16; nt++) {
                uint32_t b0 = __float_as_uint(vs[(kb2 + t) * VSTR + nt * 8 + g]);
                uint32_t b1 = __float_as_uint(vs[(kb2 + t + 4) * VSTR + nt * 8 + g]);
                mma_tf32(o[nt], a, b0, b1);
            }
        }
        __syncwarp();
        __syncthreads();
    }

    float inv0 = 1.f / l_[0], inv1 = 1.f / l_[1];
    const size_t gr0 = (size_t)b * SS + qb * 64 + w * 16 + g;
#pragma unroll
    for (int nt = 0; nt < 16; nt++) {
        int col = h * 128 + nt * 8 + 2 * t;
        O[gr0 * DD + col] = rtf(o[nt][0] * inv0);
        O[gr0 * DD + col + 1] = rtf(o[nt][1] * inv0);
        O[(gr0 + 8) * DD + col] = rtf(o[nt][2] * inv1);
        O[(gr0 + 8) * DD + col + 1] = rtf(o[nt][3] * inv1);
    }
}

extern "C" void kernel_launch(void* const* d_in, const int* in_sizes, int n_in,
                              void* d_out, int out_size)
{
    (void)in_sizes; (void)n_in; (void)out_size;
    const float* x    = (const float*)d_in[0];
    const float* anw  = (const float*)d_in[1];
    const float* anb  = (const float*)d_in[2];
    const float* Wdq  = (const float*)d_in[3];
    const float* qlw  = (const float*)d_in[4];
    const float* qlb  = (const float*)d_in[5];
    const float* Wuq  = (const float*)d_in[6];
    const float* Wdkv = (const float*)d_in[7];
    const float* klw  = (const float*)d_in[8];
    const float* klb  = (const float*)d_in[9];
    const float* Wukv = (const float*)d_in[10];
    const float* Wo   = (const float*)d_in[11];
    const float* fnw  = (const float*)d_in[12];
    const float* fnb  = (const float*)d_in[13];
    const float* W1   = (const float*)d_in[14];
    const float* b1   = (const float*)d_in[15];
    const float* W2   = (const float*)d_in[16];
    const float* b2   = (const float*)d_in[17];

    float* out = (float*)d_out;
    float* ckv = out + (size_t)MMr * DD;

    float *ph, *pcq, *pqraw, *pkvl, *pkvraw, *pq, *pk, *pv, *po, *px2, *pwoT, *pwdkvp;
    float *pwdqc, *pwuqc, *pwukvc;
    __half *pw1t, *pw2t, *phf, *pff1f;
    cudaGetSymbolAddress((void**)&ph, g_h);
    cudaGetSymbolAddress((void**)&pcq, g_cq);
    cudaGetSymbolAddress((void**)&pqraw, g_qraw);
    cudaGetSymbolAddress((void**)&pkvl, g_kvlora);
    cudaGetSymbolAddress((void**)&pkvraw, g_kvraw);
    cudaGetSymbolAddress((void**)&pq, g_q);
    cudaGetSymbolAddress((void**)&pk, g_k);
    cudaGetSymbolAddress((void**)&pv, g_v);
    cudaGetSymbolAddress((void**)&po, g_o);
    cudaGetSymbolAddress((void**)&px2, g_x2);
    cudaGetSymbolAddress((void**)&pwoT, g_woT);
    cudaGetSymbolAddress((void**)&pwdkvp, g_wdkvp);
    cudaGetSymbolAddress((void**)&pwdqc, g_wdqc);
    cudaGetSymbolAddress((void**)&pwuqc, g_wuqc);
    cudaGetSymbolAddress((void**)&pwukvc, g_wukvc);
    cudaGetSymbolAddress((void**)&pw1t, g_w1t);
    cudaGetSymbolAddress((void**)&pw2t, g_w2t);
    cudaGetSymbolAddress((void**)&phf, g_hf);
    cudaGetSymbolAddress((void**)&pff1f, g_ff1f);

    cudaFuncSetAttribute(gemm_kernel<0>, cudaFuncAttributeMaxDynamicSharedMemorySize, GEMM_SMEM);
    cudaFuncSetAttribute(gemm_kernel<2>, cudaFuncAttributeMaxDynamicSharedMemorySize, GEMM_SMEM);
    cudaFuncSetAttribute(gemm_h<1>, cudaFuncAttributeMaxDynamicSharedMemorySize, GEMMH_SMEM);
    cudaFuncSetAttribute(gemm_h<2>, cudaFuncAttributeMaxDynamicSharedMemorySize, GEMMH_SMEM);
    cudaFuncSetAttribute(attn_kernel, cudaFuncAttributeMaxDynamicSharedMemorySize, ATTN_SMEM);

    dim3 blk(256);
    dim3 t32x8(32, 8);
    freqs_kernel<<<1, 32>>>();
    ln_kernel<<<MMr, 256, DD * 4>>>(x, DD, DD, anw, anb, ph, DD, DD);
    transpose_kernel<<<dim3(64, 64), t32x8>>>(Wo, pwoT, DD);
    pad_wdkv_kernel<<<DD, 256>>>(Wdkv, pwdkvp);
    cvtw_kernel<<<4096, 256>>>(Wdq, pwdqc, Wuq, pwuqc, Wukv, pwukvc);
    tconv_h_kernel<<<dim3(64, 256), t32x8>>>(W1, DD, FFd, pw1t);
    tconv_h_kernel<<<dim3(256, 64), t32x8>>>(W2, FFd, DD, pw2t);

    // cq_raw = h @ W_dq
    gemm_kernel<0><<<dim3(QPd / BN, MMr / BM), blk, GEMM_SMEM>>>(
        ph, DD, DD, pwdqc, QPd, QPd, pcq, QPd, MMr, QPd, DD, nullptr, nullptr, 0);
    // ckv = h @ W_dkv
    gemm_kernel<0><<<dim3((CKVN + BN - 1) / BN, MMr / BM), blk, GEMM_SMEM>>>(
        ph, DD, DD, pwdkvp, WDKV_PAD, WDKV_PAD, ckv, CKVN, MMr, CKVN, DD, nullptr, nullptr, 0);
    ln_kernel<<<MMr, 256, QPd * 4>>>(pcq, QPd, QPd, qlw, qlb, pcq, QPd, QPd);
    ln_kernel<<<MMr, 256, KVPd * 4>>>(ckv, CKVN, KVPd, klw, klb, pkvl, KVL_PAD, KVL_PAD);
    // Q_raw = cq @ W_uq
    gemm_kernel<0><<<dim3(DD / BN, MMr / BM), blk, GEMM_SMEM>>>(
        pcq, QPd, QPd, pwuqc, DD, DD, pqraw, DD, MMr, DD, QPd, nullptr, nullptr, 0);
    // KV_raw = kv_lora @ W_ukv
    gemm_kernel<0><<<dim3(3072 / BN, MMr / BM), blk, GEMM_SMEM>>>(
        pkvl, KVL_PAD, KVL_PAD, pwukvc, 3072, 3072, pkvraw, 3072, MMr, 3072, KVPd, nullptr, nullptr, 0);

    rope_q_kernel<<<MMr, 256>>>(pqraw, pq);
    reorder_kv_kernel<<<MMr, 256>>>(pkvraw, ckv, pk, pv);
    attn_kernel<<<dim3(SS / 64, BB * HH), 128, ATTN_SMEM>>>(pq, pk, pv, po);

    // x2 = x + o @ Wo^T  (tf32)
    gemm_kernel<2><<<dim3(DD / BN, MMr / BM), blk, GEMM_SMEM>>>(
        po, DD, DD, pwoT, DD, DD, px2, DD, MMr, DD, DD, nullptr, x, DD);
    // FF in f16 probe
    ln_h_kernel<<<MMr, 256, DD * 4>>>(px2, DD, fnw, fnb, phf);
    gemm_h<1><<<dim3(FFd / 128, MMr / 128), blk, GEMMH_SMEM>>>(
        phf, DD, pw1t, DD, nullptr, pff1f, FFd, FFd, DD, b1, nullptr, 0);
    gemm_h<2><<<dim3(DD / 128, MMr / 128), blk, GEMMH_SMEM>>>(
        pff1f, FFd, pw2t, FFd, out, nullptr, DD, DD, FFd, b2, px2, DD);
}

// round 13
// speedup vs baseline: 1.7742x; 1.0282x over previous
#include <cuda_runtime.h>
#include <cuda_fp16.h>
#include <math.h>
#include <stdint.h>

#define BB 2
#define SS 2048
#define DD 2048
#define HH 16
#define QPd 1024
#define KVPd 1365
#define CKVN 1429
#define FFd 8192
#define MMr 4096
#define KVL_PAD 1376
#define DKV_NPAD 1536

// fp32 scratch
__device__ float g_cq[(size_t)MMr * QPd];
__device__ float g_qraw[(size_t)MMr * DD];
__device__ float g_kvraw[(size_t)MMr * 3072];
__device__ float g_q[(size_t)MMr * DD];
__device__ float g_k[(size_t)MMr * DD];
__device__ float g_v[(size_t)MMr * DD];
__device__ float g_x2[(size_t)MMr * DD];
__device__ float g_freqs[32];
// f16 activations
__device__ __half g_hf[(size_t)MMr * DD];
__device__ __half g_cqf[(size_t)MMr * QPd];
__device__ __half g_kvlf[(size_t)MMr * KVL_PAD];
__device__ __half g_of[(size_t)MMr * DD];
__device__ __half g_ff1f[(size_t)MMr * FFd];
// f16 weights [N,K]
__device__ __half g_dqt[(size_t)QPd * DD];
__device__ __half g_dkvt[(size_t)DKV_NPAD * DD];
__device__ __half g_uqt[(size_t)DD * QPd];
__device__ __half g_ukvt[(size_t)3072 * KVL_PAD];
__device__ __half g_w1t[(size_t)FFd * DD];
__device__ __half g_w2t[(size_t)DD * FFd];
__device__ __half g_wof[(size_t)DD * DD];

__device__ __forceinline__ uint32_t f2tf(float x) {
    uint32_t u;
    asm("cvt.rna.tf32.f32 %0, %1;" : "=r"(u) : "f"(x));
    return u;
}
__device__ __forceinline__ float rtf(float x) { return __uint_as_float(f2tf(x)); }

__device__ __forceinline__ void mma_tf32(float* c, const uint32_t* a, uint32_t b0, uint32_t b1) {
    asm volatile(
        "mma.sync.aligned.m16n8k8.row.col.f32.tf32.tf32.f32 "
        "{%0,%1,%2,%3}, {%4,%5,%6,%7}, {%8,%9}, {%0,%1,%2,%3};"
        : "+f"(c[0]), "+f"(c[1]), "+f"(c[2]), "+f"(c[3])
        : "r"(a[0]), "r"(a[1]), "r"(a[2]), "r"(a[3]), "r"(b0), "r"(b1));
}
__device__ __forceinline__ void mma_h(uint32_t& d0, uint32_t& d1, const uint32_t* a,
                                      uint32_t b0, uint32_t b1, uint32_t c0, uint32_t c1) {
    asm volatile(
        "mma.sync.aligned.m16n8k16.row.col.f16.f16.f16.f16 "
        "{%0,%1}, {%2,%3,%4,%5}, {%6,%7}, {%8,%9};"
        : "=r"(d0), "=r"(d1)
        : "r"(a[0]), "r"(a[1]), "r"(a[2]), "r"(a[3]), "r"(b0), "r"(b1), "r"(c0), "r"(c1));
}
__device__ __forceinline__ void cp16(void* dst, const void* src) {
    uint32_t d = (uint32_t)__cvta_generic_to_shared(dst);
    asm volatile("cp.async.cg.shared.global [%0], [%1], 16;" :: "r"(d), "l"(src));
}

// ================= f16 GEMM: C[M,N] = A[M,K] @ B[N,K]^T =================
#define HSTR 40
#define HT_ELE (128 * HSTR)
#define GEMMH_SMEM (4 * HT_ELE * 2)

// EPI: 0 fp32 out ; 1 bias+GELU -> f16 out ; 2 (opt bias)+residual -> fp32 out
template <int EPI>
__global__ __launch_bounds__(256) void gemm_h(
    const __half* __restrict__ A, int lda,
    const __half* __restrict__ B, int ldb,
    float* __restrict__ C, __half* __restrict__ Ch, int ldc,
    int N, int K,
    const float* __restrict__ bias, const float* __restrict__ res, int ldres)
{
    extern __shared__ __half smh[];
    __half* As = smh;
    __half* Bs = smh + 2 * HT_ELE;
    const int tid = threadIdx.x, lane = tid & 31, warp = tid >> 5;
    const int wm = warp >> 1, wn = warp & 1;
    const int bm0 = blockIdx.y * 128, bn0 = blockIdx.x * 128;
    const int g = lane >> 2, t = lane & 3;

    float acc[2][8][4];
#pragma unroll
    for (int i = 0; i < 2; i++)
#pragma unroll
        for (int j = 0; j < 8; j++)
#pragma unroll
            for (int c = 0; c < 4; c++) acc[i][j][c] = 0.f;

    const int KT = K / 32;
    auto load_tiles = [&](int buf, int k0) {
        __half* Ab = As + buf * HT_ELE;
        __half* Bb = Bs + buf * HT_ELE;
#pragma unroll
        for (int i = 0; i < 2; i++) {
            int idx = i * 256 + tid;
            int r = idx >> 2, s = idx & 3;
            cp16(Ab + r * HSTR + s * 8, A + (size_t)(bm0 + r) * lda + k0 + s * 8);
        }
#pragma unroll
        for (int i = 0; i < 2; i++) {
            int idx = i * 256 + tid;
            int r = idx >> 2, s = idx & 3;
            cp16(Bb + r * HSTR + s * 8, B + (size_t)(bn0 + r) * ldb + k0 + s * 8);
        }
        asm volatile("cp.async.commit_group;");
    };

    load_tiles(0, 0);
    int buf = 0;
    for (int kt = 0; kt < KT; kt++) {
        if (kt + 1 < KT) {
            load_tiles(buf ^ 1, (kt + 1) * 32);
            asm volatile("cp.async.wait_group 1;");
        } else {
            asm volatile("cp.async.wait_group 0;");
        }
        __syncthreads();
        const __half* Ab = As + buf * HT_ELE;
        const __half* Bb = Bs + buf * HT_ELE;

        uint32_t af[2][2][4];
#pragma unroll
        for (int ks = 0; ks < 2; ks++) {
            const int kb = ks * 16 + 2 * t;
#pragma unroll
            for (int im = 0; im < 2; im++) {
                const int r = wm * 32 + im * 16 + g;
                af[ks][im][0] = *(const uint32_t*)(Ab + r * HSTR + kb);
                af[ks][im][1] = *(const uint32_t*)(Ab + (r + 8) * HSTR + kb);
                af[ks][im][2] = *(const uint32_t*)(Ab + r * HSTR + kb + 8);
                af[ks][im][3] = *(const uint32_t*)(Ab + (r + 8) * HSTR + kb + 8);
            }
        }
#pragma unroll
        for (int nt = 0; nt < 8; nt++) {
            const int c = wn * 64 + nt * 8 + g;
            uint32_t b00 = *(const uint32_t*)(Bb + c * HSTR + 2 * t);
            uint32_t b01 = *(const uint32_t*)(Bb + c * HSTR + 2 * t + 8);
            uint32_t b10 = *(const uint32_t*)(Bb + c * HSTR + 16 + 2 * t);
            uint32_t b11 = *(const uint32_t*)(Bb + c * HSTR + 16 + 2 * t + 8);
#pragma unroll
            for (int im = 0; im < 2; im++) {
                uint32_t d0, d1, e0, e1;
                mma_h(d0, d1, af[0][im], b00, b01, 0u, 0u);
                mma_h(e0, e1, af[1][im], b10, b11, d0, d1);
                float2 p0 = __half22float2(*reinterpret_cast<__half2*>(&e0));
                float2 p1 = __half22float2(*reinterpret_cast<__half2*>(&e1));
                acc[im][nt][0] += p0.x;
                acc[im][nt][1] += p0.y;
                acc[im][nt][2] += p1.x;
                acc[im][nt][3] += p1.y;
            }
        }
        __syncthreads();
        buf ^= 1;
    }
#pragma unroll
    for (int im = 0; im < 2; im++)
#pragma unroll
        for (int nt = 0; nt < 8; nt++) {
            const int r0 = bm0 + wm * 32 + im * 16 + g;
            const int c0 = bn0 + wn * 64 + nt * 8 + 2 * t;
#pragma unroll
            for (int e = 0; e < 4; e++) {
                int r = r0 + (e >> 1) * 8;
                int c = c0 + (e & 1);
                if (c < N) {
                    float v = acc[im][nt][e];
                    if (EPI == 0) {
                        C[(size_t)r * ldc + c] = v;
                    } else if (EPI == 1) {
                        v += bias[c];
                        v = 0.5f * v * (1.f + erff(v * 0.7071067811865475f));
                        Ch[(size_t)r * ldc + c] = __float2half_rn(v);
                    } else {
                        if (bias) v += bias[c];
                        v += res[(size_t)r * ldres + c];
                        C[(size_t)r * ldc + c] = v;
                    }
                }
            }
        }
}

// ================= LayerNorm -> f16 =================
__global__ void ln_h_kernel(const float* __restrict__ in, int ldin, int cols,
                            const float* __restrict__ w, const float* __restrict__ b,
                            __half* __restrict__ out, int ldout, int padto)
{
    extern __shared__ float sbuf[];
    __shared__ float red[8];
    __shared__ float bc[2];
    const int row = blockIdx.x, tid = threadIdx.x, lane = tid & 31, warp = tid >> 5;
    const float* ip = in + (size_t)row * ldin;
    float s = 0.f;
    for (int c = tid; c < cols; c += 256) { float v = ip[c]; sbuf[c] = v; s += v; }
#pragma unroll
    for (int o = 16; o > 0; o >>= 1) s += __shfl_xor_sync(0xffffffffu, s, o);
    if (lane == 0) red[warp] = s;
    __syncthreads();
    if (tid == 0) { float t = 0; for (int i = 0; i < 8; i++) t += red[i]; bc[0] = t / cols; }
    __syncthreads();
    float mean = bc[0], vs = 0.f;
    for (int c = tid; c < cols; c += 256) { float d = sbuf[c] - mean; vs += d * d; }
#pragma unroll
    for (int o = 16; o > 0; o >>= 1) vs += __shfl_xor_sync(0xffffffffu, vs, o);
    if (lane == 0) red[warp] = vs;
    __syncthreads();
    if (tid == 0) { float t = 0; for (int i = 0; i < 8; i++) t += red[i]; bc[1] = rsqrtf(t / cols + 1e-5f); }
    __syncthreads();
    float inv = bc[1];
    __half* op = out + (size_t)row * ldout;
    for (int c = tid; c < cols; c += 256) op[c] = __float2half_rn((sbuf[c] - mean) * inv * w[c] + b[c]);
    for (int c = cols + tid; c < padto; c += 256) op[c] = __float2half_rn(0.f);
}

__global__ void freqs_kernel() {
    int j = threadIdx.x;
    if (j < 32) g_freqs[j] = (float)exp(-(double)j * 0.14391156831212787);
}

// [K,N] fp32 -> [Npad,Kpad] f16 transpose-convert, zero-padded. Grid: (Kpad/32, Npad/32)
__global__ void tconv_h_kernel(const float* __restrict__ in, int K, int N, int Kpad,
                               __half* __restrict__ out)
{
    __shared__ float tb[32][33];
    const int k0 = blockIdx.x * 32, n0 = blockIdx.y * 32;
    const int tx = threadIdx.x, ty = threadIdx.y;
#pragma unroll
    for (int i = 0; i < 32; i += 8) {
        int k = k0 + ty + i, n = n0 + tx;
        tb[ty + i][tx] = (k < K && n < N) ? in[(size_t)k * N + n] : 0.f;
    }
    __syncthreads();
#pragma unroll
    for (int i = 0; i < 32; i += 8)
        out[(size_t)(n0 + ty + i) * Kpad + k0 + tx] = __float2half_rn(tb[tx][ty + i]);
}

__global__ void wof_kernel(const float* __restrict__ in, __half* __restrict__ out) {
    size_t i = (size_t)blockIdx.x * blockDim.x + threadIdx.x;
    if (i < (size_t)DD * DD) out[i] = __float2half_rn(in[i]);
}

__global__ void rope_q_kernel(const float* __restrict__ qraw, float* __restrict__ qout) {
    int bs = blockIdx.x;
    int s = bs & (SS - 1), b = bs >> 11;
    for (int i = threadIdx.x; i < DD; i += 256) {
        int hh = i >> 7, d = i & 127;
        const float* src = qraw + (size_t)bs * DD + hh * 128;
        float v;
        if (d < 64) {
            v = src[d];
        } else {
            int dd = d - 64;
            int j = dd & 31;
            float t = (float)s * g_freqs[j];
            float x = src[64 + dd];
            float rx = (dd < 32) ? -src[64 + dd + 32] : src[64 + dd - 32];
            v = x * cosf(t) + rx * sinf(t);
        }
        qout[(((size_t)b * HH + hh) * SS + s) * 128 + d] = rtf(v);
    }
}

__global__ void reorder_kv_kernel(const float* __restrict__ kvraw, const float* __restrict__ ckv,
                                  float* __restrict__ kout, float* __restrict__ vout) {
    __shared__ float kr[64];
    int bs = blockIdx.x;
    int s = bs & (SS - 1), b = bs >> 11;
    int tid = threadIdx.x;
    if (tid < 64) {
        int dd = tid, j = dd & 31;
        float t = (float)s * g_freqs[j];
        const float* src = ckv + (size_t)bs * CKVN + KVPd;
        float x = src[dd];
        float rx = (dd < 32) ? -src[dd + 32] : src[dd - 32];
        kr[dd] = rtf(x * cosf(t) + rx * sinf(t));
    }
    __syncthreads();
    for (int i = tid; i < HH * 192; i += 256) {
        int hh = i / 192, d = i % 192;
        float v = rtf(kvraw[(size_t)bs * 3072 + i]);
        size_t base = (((size_t)b * HH + hh) * SS + s) * 128;
        if (d < 64) kout[base + d] = v;
        else vout[base + (d - 64)] = v;
    }
    for (int i = tid; i < HH * 64; i += 256) {
        int hh = i >> 6, dd = i & 63;
        kout[(((size_t)b * HH + hh) * SS + s) * 128 + 64 + dd] = kr[dd];
    }
}

// ================= attention (tf32), outputs f16 =================
#define QSTR 132
#define VSTR 136
#define ATTN_SMEM ((64 * QSTR + 32 * QSTR + 32 * VSTR + 4 * 16 * 36) * 4)

__global__ __launch_bounds__(128) void attn_kernel(
    const float* __restrict__ Q, const float* __restrict__ Kk,
    const float* __restrict__ V, __half* __restrict__ O)
{
    extern __shared__ float smema[];
    float* qs = smema;
    float* ks = qs + 64 * QSTR;
    float* vs = ks + 32 * QSTR;
    float* ps = vs + 32 * VSTR;
    const int qb = blockIdx.x, bh = blockIdx.y;
    const int b = bh >> 4, h = bh & 15;
    const int tid = threadIdx.x, lane = tid & 31, w = tid >> 5;
    const int g = lane >> 2, t = lane & 3;

    const float* Qb = Q + ((size_t)bh * SS + qb * 64) * 128;
    const float* Kb = Kk + (size_t)bh * SS * 128;
    const float* Vb = V + (size_t)bh * SS * 128;

    for (int i = tid; i < 64 * 32; i += 128) {
        int r = i >> 5, c4 = (i & 31) * 4;
        *(float4*)(qs + r * QSTR + c4) = *(const float4*)(Qb + r * 128 + c4);
    }
    __syncthreads();

    float m_[2] = {-1e30f, -1e30f};
    float l_[2] = {0.f, 0.f};
    float o[16][4];
#pragma unroll
    for (int i = 0; i < 16; i++)
#pragma unroll
        for (int c = 0; c < 4; c++) o[i][c] = 0.f;

    const int nkt = qb * 2 + 2;
    const float scale = 0.08838834764831845f;
    float* pw = ps + w * 16 * 36;

    for (int kt = 0; kt < nkt; kt++) {
        for (int i = tid; i < 32 * 32; i += 128) {
            int r = i >> 5, c4 = (i & 31) * 4;
            *(float4*)(ks + r * QSTR + c4) = *(const float4*)(Kb + ((size_t)kt * 32 + r) * 128 + c4);
            *(float4*)(vs + r * VSTR + c4) = *(const float4*)(Vb + ((size_t)kt * 32 + r) * 128 + c4);
        }
        __syncthreads();

        float s[4][4];
#pragma unroll
        for (int nt = 0; nt < 4; nt++)
#pragma unroll
            for (int c = 0; c < 4; c++) s[nt][c] = 0.f;

#pragma unroll
        for (int k8 = 0; k8 < 16; k8++) {
            const int kb2 = k8 * 8;
            uint32_t a[4];
            const int rb = w * 16;
            a[0] = __float_as_uint(qs[(rb + g) * QSTR + kb2 + t]);
            a[1] = __float_as_uint(qs[(rb + g + 8) * QSTR + kb2 + t]);
            a[2] = __float_as_uint(qs[(rb + g) * QSTR + kb2 + t + 4]);
            a[3] = __float_as_uint(qs[(rb + g + 8) * QSTR + kb2 + t + 4]);
#pragma unroll
            for (int nt = 0; nt < 4; nt++) {
                uint32_t b0 = __float_as_uint(ks[(nt * 8 + g) * QSTR + kb2 + t]);
                uint32_t b1 = __float_as_uint(ks[(nt * 8 + g) * QSTR + kb2 + t + 4]);
                mma_tf32(s[nt], a, b0, b1);
            }
        }

        const int qrow0 = qb * 64 + w * 16 + g;
        const int qrow1 = qrow0 + 8;
#pragma unroll
        for (int nt = 0; nt < 4; nt++)
#pragma unroll
            for (int c = 0; c < 4; c++) {
                int row = (c < 2) ? qrow0 : qrow1;
                int kidx = kt * 32 + nt * 8 + 2 * t + (c & 1);
                float v = s[nt][c] * scale;
                if (kidx > row) v = -1e30f;
                s[nt][c] = v;
            }

        float mx0 = -1e30f, mx1 = -1e30f;
#pragma unroll
        for (int nt = 0; nt < 4; nt++) {
            mx0 = fmaxf(mx0, fmaxf(s[nt][0], s[nt][1]));
            mx1 = fmaxf(mx1, fmaxf(s[nt][2], s[nt][3]));
        }
#pragma unroll
        for (int off = 1; off < 4; off <<= 1) {
            mx0 = fmaxf(mx0, __shfl_xor_sync(0xffffffffu, mx0, off));
            mx1 = fmaxf(mx1, __shfl_xor_sync(0xffffffffu, mx1, off));
        }
        float mn0 = fmaxf(m_[0], mx0), mn1 = fmaxf(m_[1], mx1);
        float al0 = expf(m_[0] - mn0), al1 = expf(m_[1] - mn1);
        float rs0 = 0.f, rs1 = 0.f;
#pragma unroll
        for (int nt = 0; nt < 4; nt++) {
            s[nt][0] = expf(s[nt][0] - mn0);
            s[nt][1] = expf(s[nt][1] - mn0);
            s[nt][2] = expf(s[nt][2] - mn1);
            s[nt][3] = expf(s[nt][3] - mn1);
            rs0 += s[nt][0] + s[nt][1];
            rs1 += s[nt][2] + s[nt][3];
        }
#pragma unroll
        for (int off = 1; off < 4; off <<= 1) {
            rs0 += __shfl_xor_sync(0xffffffffu, rs0, off);
            rs1 += __shfl_xor_sync(0xffffffffu, rs1, off);
        }
        l_[0] = l_[0] * al0 + rs0;
        l_[1] = l_[1] * al1 + rs1;
        m_[0] = mn0; m_[1] = mn1;
#pragma unroll
        for (int nt = 0; nt < 16; nt++) {
            o[nt][0] *= al0; o[nt][1] *= al0;
            o[nt][2] *= al1; o[nt][3] *= al1;
        }

#pragma unroll
        for (int nt = 0; nt < 4; nt++) {
            pw[g * 36 + nt * 8 + 2 * t] = rtf(s[nt][0]);
            pw[g * 36 + nt * 8 + 2 * t + 1] = rtf(s[nt][1]);
            pw[(g + 8) * 36 + nt * 8 + 2 * t] = rtf(s[nt][2]);
            pw[(g + 8) * 36 + nt * 8 + 2 * t + 1] = rtf(s[nt][3]);
        }
        __syncwarp();

#pragma unroll
        for (int k8 = 0; k8 < 4; k8++) {
            const int kb2 = k8 * 8;
            uint32_t a[4];
            a[0] = __float_as_uint(pw[g * 36 + kb2 + t]);
            a[1] = __float_as_uint(pw[(g + 8) * 36 + kb2 + t]);
            a[2] = __float_as_uint(pw[g * 36 + kb2 + t + 4]);
            a[3] = __float_as_uint(pw[(g + 8) * 36 + kb2 + t + 4]);
#pragma unroll
            for (int nt = 0; nt < 16; nt++) {
                uint32_t b0 = __float_as_uint(vs[(kb2 + t) * VSTR + nt * 8 + g]);
                uint32_t b1 = __float_as_uint(vs[(kb2 + t + 4) * VSTR + nt * 8 + g]);
                mma_tf32(o[nt], a, b0, b1);
            }
        }
        __syncwarp();
        __syncthreads();
    }

    float inv0 = 1.f / l_[0], inv1 = 1.f / l_[1];
    const size_t gr0 = (size_t)b * SS + qb * 64 + w * 16 + g;
#pragma unroll
    for (int nt = 0; nt < 16; nt++) {
        int col = h * 128 + nt * 8 + 2 * t;
        O[gr0 * DD + col] = __float2half_rn(o[nt][0] * inv0);
        O[gr0 * DD + col + 1] = __float2half_rn(o[nt][1] * inv0);
        O[(gr0 + 8) * DD + col] = __float2half_rn(o[nt][2] * inv1);
        O[(gr0 + 8) * DD + col + 1] = __float2half_rn(o[nt][3] * inv1);
    }
}

extern "C" void kernel_launch(void* const* d_in, const int* in_sizes, int n_in,
                              void* d_out, int out_size)
{
    (void)in_sizes; (void)n_in; (void)out_size;
    const float* x    = (const float*)d_in[0];
    const float* anw  = (const float*)d_in[1];
    const float* anb  = (const float*)d_in[2];
    const float* Wdq  = (const float*)d_in[3];
    const float* qlw  = (const float*)d_in[4];
    const float* qlb  = (const float*)d_in[5];
    const float* Wuq  = (const float*)d_in[6];
    const float* Wdkv = (const float*)d_in[7];
    const float* klw  = (const float*)d_in[8];
    const float* klb  = (const float*)d_in[9];
    const float* Wukv = (const float*)d_in[10];
    const float* Wo   = (const float*)d_in[11];
    const float* fnw  = (const float*)d_in[12];
    const float* fnb  = (const float*)d_in[13];
    const float* W1   = (const float*)d_in[14];
    const float* b1   = (const float*)d_in[15];
    const float* W2   = (const float*)d_in[16];
    const float* b2   = (const float*)d_in[17];

    float* out = (float*)d_out;
    float* ckv = out + (size_t)MMr * DD;

    float *pcq, *pqraw, *pkvraw, *pq, *pk, *pv, *px2;
    __half *phf, *pcqf, *pkvlf, *pof, *pff1f;
    __half *pdqt, *pdkvt, *puqt, *pukvt, *pw1t, *pw2t, *pwof;
    cudaGetSymbolAddress((void**)&pcq, g_cq);
    cudaGetSymbolAddress((void**)&pqraw, g_qraw);
    cudaGetSymbolAddress((void**)&pkvraw, g_kvraw);
    cudaGetSymbolAddress((void**)&pq, g_q);
    cudaGetSymbolAddress((void**)&pk, g_k);
    cudaGetSymbolAddress((void**)&pv, g_v);
    cudaGetSymbolAddress((void**)&px2, g_x2);
    cudaGetSymbolAddress((void**)&phf, g_hf);
    cudaGetSymbolAddress((void**)&pcqf, g_cqf);
    cudaGetSymbolAddress((void**)&pkvlf, g_kvlf);
    cudaGetSymbolAddress((void**)&pof, g_of);
    cudaGetSymbolAddress((void**)&pff1f, g_ff1f);
    cudaGetSymbolAddress((void**)&pdqt, g_dqt);
    cudaGetSymbolAddress((void**)&pdkvt, g_dkvt);
    cudaGetSymbolAddress((void**)&puqt, g_uqt);
    cudaGetSymbolAddress((void**)&pukvt, g_ukvt);
    cudaGetSymbolAddress((void**)&pw1t, g_w1t);
    cudaGetSymbolAddress((void**)&pw2t, g_w2t);
    cudaGetSymbolAddress((void**)&pwof, g_wof);

    cudaFuncSetAttribute(gemm_h<0>, cudaFuncAttributeMaxDynamicSharedMemorySize, GEMMH_SMEM);
    cudaFuncSetAttribute(gemm_h<1>, cudaFuncAttributeMaxDynamicSharedMemorySize, GEMMH_SMEM);
    cudaFuncSetAttribute(gemm_h<2>, cudaFuncAttributeMaxDynamicSharedMemorySize, GEMMH_SMEM);
    cudaFuncSetAttribute(attn_kernel, cudaFuncAttributeMaxDynamicSharedMemorySize, ATTN_SMEM);

    dim3 blk(256);
    dim3 t32x8(32, 8);
    freqs_kernel<<<1, 32>>>();
    ln_h_kernel<<<MMr, 256, DD * 4>>>(x, DD, DD, anw, anb, phf, DD, DD);
    tconv_h_kernel<<<dim3(64, 32), t32x8>>>(Wdq, DD, QPd, DD, pdqt);
    tconv_h_kernel<<<dim3(64, 48), t32x8>>>(Wdkv, DD, CKVN, DD, pdkvt);
    tconv_h_kernel<<<dim3(32, 64), t32x8>>>(Wuq, QPd, DD, QPd, puqt);
    tconv_h_kernel<<<dim3(43, 96), t32x8>>>(Wukv, KVPd, 3072, KVL_PAD, pukvt);
    tconv_h_kernel<<<dim3(64, 256), t32x8>>>(W1, DD, FFd, DD, pw1t);
    tconv_h_kernel<<<dim3(256, 64), t32x8>>>(W2, FFd, DD, FFd, pw2t);
    wof_kernel<<<(DD * DD + 255) / 256, 256>>>(Wo, pwof);

    // cq_raw = h @ W_dq
    gemm_h<0><<<dim3(QPd / 128, MMr / 128), blk, GEMMH_SMEM>>>(
        phf, DD, pdqt, DD, pcq, nullptr, QPd, QPd, DD, nullptr, nullptr, 0);
    // ckv = h @ W_dkv (N=1429 guarded)
    gemm_h<0><<<dim3(DKV_NPAD / 128, MMr / 128), blk, GEMMH_SMEM>>>(
        phf, DD, pdkvt, DD, ckv, nullptr, CKVN, CKVN, DD, nullptr, nullptr, 0);
    ln_h_kernel<<<MMr, 256, QPd * 4>>>(pcq, QPd, QPd, qlw, qlb, pcqf, QPd, QPd);
    ln_h_kernel<<<MMr, 256, KVPd * 4>>>(ckv, CKVN, KVPd, klw, klb, pkvlf, KVL_PAD, KVL_PAD);
    // Q_raw = cq @ W_uq
    gemm_h<0><<<dim3(DD / 128, MMr / 128), blk, GEMMH_SMEM>>>(
        pcqf, QPd, puqt, QPd, pqraw, nullptr, DD, DD, QPd, nullptr, nullptr, 0);
    // KV_raw = kv_lora @ W_ukv
    gemm_h<0><<<dim3(3072 / 128, MMr / 128), blk, GEMMH_SMEM>>>(
        pkvlf, KVL_PAD, pukvt, KVL_PAD, pkvraw, nullptr, 3072, 3072, KVL_PAD, nullptr, nullptr, 0);

    rope_q_kernel<<<MMr, 256>>>(pqraw, pq);
    reorder_kv_kernel<<<MMr, 256>>>(pkvraw, ckv, pk, pv);
    attn_kernel<<<dim3(SS / 64, BB * HH), 128, ATTN_SMEM>>>(pq, pk, pv, pof);

    // x2 = x + o @ Wo^T
    gemm_h<2><<<dim3(DD / 128, MMr / 128), blk, GEMMH_SMEM>>>(
        pof, DD, pwof, DD, px2, nullptr, DD, DD, DD, nullptr, x, DD);
    ln_h_kernel<<<MMr, 256, DD * 4>>>(px2, DD, DD, fnw, fnb, phf, DD, DD);
    // ff1 = gelu(h @ W1 + b1) -> f16
    gemm_h<1><<<dim3(FFd / 128, MMr / 128), blk, GEMMH_SMEM>>>(
        phf, DD, pw1t, DD, nullptr, pff1f, FFd, FFd, DD, b1, nullptr, 0);
    // out = x2 + ff1 @ W2 + b2
    gemm_h<2><<<dim3(DD / 128, MMr / 128), blk, GEMMH_SMEM>>>(
        pff1f, FFd, pw2t, FFd, out, nullptr, DD, DD, FFd, b2, px2, DD);
}

// round 14
// speedup vs baseline: 1.9851x; 1.1188x over previous
#include <cuda_runtime.h>
#include <cuda_fp16.h>
#include <math.h>
#include <stdint.h>

#define BB 2
#define SS 2048
#define DD 2048
#define HH 16
#define QPd 1024
#define KVPd 1365
#define CKVN 1429
#define FFd 8192
#define MMr 4096
#define KVL_PAD 1376
#define DKV_NPAD 1536

// fp32 scratch
__device__ float g_cq[(size_t)MMr * QPd];
__device__ float g_qraw[(size_t)MMr * DD];
__device__ float g_kvraw[(size_t)MMr * 3072];
__device__ float g_x2[(size_t)MMr * DD];
__device__ float g_freqs[32];
// f16 activations
__device__ __half g_hf[(size_t)MMr * DD];
__device__ __half g_cqf[(size_t)MMr * QPd];
__device__ __half g_kvlf[(size_t)MMr * KVL_PAD];
__device__ __half g_of[(size_t)MMr * DD];
__device__ __half g_ff1f[(size_t)MMr * FFd];
__device__ __half g_qh[(size_t)MMr * DD];
__device__ __half g_kh[(size_t)MMr * DD];
__device__ __half g_vtmp[(size_t)MMr * DD];
__device__ __half g_vT[(size_t)MMr * DD];
// f16 weights [N,K]
__device__ __half g_dqt[(size_t)QPd * DD];
__device__ __half g_dkvt[(size_t)DKV_NPAD * DD];
__device__ __half g_uqt[(size_t)DD * QPd];
__device__ __half g_ukvt[(size_t)3072 * KVL_PAD];
__device__ __half g_w1t[(size_t)FFd * DD];
__device__ __half g_w2t[(size_t)DD * FFd];
__device__ __half g_wof[(size_t)DD * DD];

__device__ __forceinline__ uint32_t f2tf(float x) {
    uint32_t u;
    asm("cvt.rna.tf32.f32 %0, %1;" : "=r"(u) : "f"(x));
    return u;
}
__device__ __forceinline__ float rtf(float x) { return __uint_as_float(f2tf(x)); }

__device__ __forceinline__ void mma_h(uint32_t& d0, uint32_t& d1, const uint32_t* a,
                                      uint32_t b0, uint32_t b1, uint32_t c0, uint32_t c1) {
    asm volatile(
        "mma.sync.aligned.m16n8k16.row.col.f16.f16.f16.f16 "
        "{%0,%1}, {%2,%3,%4,%5}, {%6,%7}, {%8,%9};"
        : "=r"(d0), "=r"(d1)
        : "r"(a[0]), "r"(a[1]), "r"(a[2]), "r"(a[3]), "r"(b0), "r"(b1), "r"(c0), "r"(c1));
}
__device__ __forceinline__ void cp16(void* dst, const void* src) {
    uint32_t d = (uint32_t)__cvta_generic_to_shared(dst);
    asm volatile("cp.async.cg.shared.global [%0], [%1], 16;" :: "r"(d), "l"(src));
}

// ================= f16 GEMM: C[M,N] = A[M,K] @ B[N,K]^T =================
#define HSTR 40
#define HT_ELE (128 * HSTR)
#define GEMMH_SMEM (4 * HT_ELE * 2)

// EPI: 0 fp32 out ; 1 bias+GELU -> f16 out ; 2 (opt bias)+residual -> fp32 out
template <int EPI>
__global__ __launch_bounds__(256) void gemm_h(
    const __half* __restrict__ A, int lda,
    const __half* __restrict__ B, int ldb,
    float* __restrict__ C, __half* __restrict__ Ch, int ldc,
    int N, int K,
    const float* __restrict__ bias, const float* __restrict__ res, int ldres)
{
    extern __shared__ __half smh[];
    __half* As = smh;
    __half* Bs = smh + 2 * HT_ELE;
    const int tid = threadIdx.x, lane = tid & 31, warp = tid >> 5;
    const int wm = warp >> 1, wn = warp & 1;
    const int bm0 = blockIdx.y * 128, bn0 = blockIdx.x * 128;
    const int g = lane >> 2, t = lane & 3;

    float acc[2][8][4];
#pragma unroll
    for (int i = 0; i < 2; i++)
#pragma unroll
        for (int j = 0; j < 8; j++)
#pragma unroll
            for (int c = 0; c < 4; c++) acc[i][j][c] = 0.f;

    const int KT = K / 32;
    auto load_tiles = [&](int buf, int k0) {
        __half* Ab = As + buf * HT_ELE;
        __half* Bb = Bs + buf * HT_ELE;
#pragma unroll
        for (int i = 0; i < 2; i++) {
            int idx = i * 256 + tid;
            int r = idx >> 2, s = idx & 3;
            cp16(Ab + r * HSTR + s * 8, A + (size_t)(bm0 + r) * lda + k0 + s * 8);
        }
#pragma unroll
        for (int i = 0; i < 2; i++) {
            int idx = i * 256 + tid;
            int r = idx >> 2, s = idx & 3;
            cp16(Bb + r * HSTR + s * 8, B + (size_t)(bn0 + r) * ldb + k0 + s * 8);
        }
        asm volatile("cp.async.commit_group;");
    };

    load_tiles(0, 0);
    int buf = 0;
    for (int kt = 0; kt < KT; kt++) {
        if (kt + 1 < KT) {
            load_tiles(buf ^ 1, (kt + 1) * 32);
            asm volatile("cp.async.wait_group 1;");
        } else {
            asm volatile("cp.async.wait_group 0;");
        }
        __syncthreads();
        const __half* Ab = As + buf * HT_ELE;
        const __half* Bb = Bs + buf * HT_ELE;

        uint32_t af[2][2][4];
#pragma unroll
        for (int ks = 0; ks < 2; ks++) {
            const int kb = ks * 16 + 2 * t;
#pragma unroll
            for (int im = 0; im < 2; im++) {
                const int r = wm * 32 + im * 16 + g;
                af[ks][im][0] = *(const uint32_t*)(Ab + r * HSTR + kb);
                af[ks][im][1] = *(const uint32_t*)(Ab + (r + 8) * HSTR + kb);
                af[ks][im][2] = *(const uint32_t*)(Ab + r * HSTR + kb + 8);
                af[ks][im][3] = *(const uint32_t*)(Ab + (r + 8) * HSTR + kb + 8);
            }
        }
#pragma unroll
        for (int nt = 0; nt < 8; nt++) {
            const int c = wn * 64 + nt * 8 + g;
            uint32_t b00 = *(const uint32_t*)(Bb + c * HSTR + 2 * t);
            uint32_t b01 = *(const uint32_t*)(Bb + c * HSTR + 2 * t + 8);
            uint32_t b10 = *(const uint32_t*)(Bb + c * HSTR + 16 + 2 * t);
            uint32_t b11 = *(const uint32_t*)(Bb + c * HSTR + 16 + 2 * t + 8);
#pragma unroll
            for (int im = 0; im < 2; im++) {
                uint32_t d0, d1, e0, e1;
                mma_h(d0, d1, af[0][im], b00, b01, 0u, 0u);
                mma_h(e0, e1, af[1][im], b10, b11, d0, d1);
                float2 p0 = __half22float2(*reinterpret_cast<__half2*>(&e0));
                float2 p1 = __half22float2(*reinterpret_cast<__half2*>(&e1));
                acc[im][nt][0] += p0.x;
                acc[im][nt][1] += p0.y;
                acc[im][nt][2] += p1.x;
                acc[im][nt][3] += p1.y;
            }
        }
        __syncthreads();
        buf ^= 1;
    }
#pragma unroll
    for (int im = 0; im < 2; im++)
#pragma unroll
        for (int nt = 0; nt < 8; nt++) {
            const int r0 = bm0 + wm * 32 + im * 16 + g;
            const int c0 = bn0 + wn * 64 + nt * 8 + 2 * t;
#pragma unroll
            for (int e = 0; e < 4; e++) {
                int r = r0 + (e >> 1) * 8;
                int c = c0 + (e & 1);
                if (c < N) {
                    float v = acc[im][nt][e];
                    if (EPI == 0) {
                        C[(size_t)r * ldc + c] = v;
                    } else if (EPI == 1) {
                        v += bias[c];
                        v = 0.5f * v * (1.f + erff(v * 0.7071067811865475f));
                        Ch[(size_t)r * ldc + c] = __float2half_rn(v);
                    } else {
                        if (bias) v += bias[c];
                        v += res[(size_t)r * ldres + c];
                        C[(size_t)r * ldc + c] = v;
                    }
                }
            }
        }
}

// ================= LayerNorm -> f16 =================
__global__ void ln_h_kernel(const float* __restrict__ in, int ldin, int cols,
                            const float* __restrict__ w, const float* __restrict__ b,
                            __half* __restrict__ out, int ldout, int padto)
{
    extern __shared__ float sbuf[];
    __shared__ float red[8];
    __shared__ float bc[2];
    const int row = blockIdx.x, tid = threadIdx.x, lane = tid & 31, warp = tid >> 5;
    const float* ip = in + (size_t)row * ldin;
    float s = 0.f;
    for (int c = tid; c < cols; c += 256) { float v = ip[c]; sbuf[c] = v; s += v; }
#pragma unroll
    for (int o = 16; o > 0; o >>= 1) s += __shfl_xor_sync(0xffffffffu, s, o);
    if (lane == 0) red[warp] = s;
    __syncthreads();
    if (tid == 0) { float t = 0; for (int i = 0; i < 8; i++) t += red[i]; bc[0] = t / cols; }
    __syncthreads();
    float mean = bc[0], vs = 0.f;
    for (int c = tid; c < cols; c += 256) { float d = sbuf[c] - mean; vs += d * d; }
#pragma unroll
    for (int o = 16; o > 0; o >>= 1) vs += __shfl_xor_sync(0xffffffffu, vs, o);
    if (lane == 0) red[warp] = vs;
    __syncthreads();
    if (tid == 0) { float t = 0; for (int i = 0; i < 8; i++) t += red[i]; bc[1] = rsqrtf(t / cols + 1e-5f); }
    __syncthreads();
    float inv = bc[1];
    __half* op = out + (size_t)row * ldout;
    for (int c = tid; c < cols; c += 256) op[c] = __float2half_rn((sbuf[c] - mean) * inv * w[c] + b[c]);
    for (int c = cols + tid; c < padto; c += 256) op[c] = __float2half_rn(0.f);
}

__global__ void freqs_kernel() {
    int j = threadIdx.x;
    if (j < 32) g_freqs[j] = (float)exp(-(double)j * 0.14391156831212787);
}

// [K,N] fp32 -> [Npad,Kpad] f16 transpose-convert, zero-padded. Grid: (Kpad/32, Npad/32)
__global__ void tconv_h_kernel(const float* __restrict__ in, int K, int N, int Kpad,
                               __half* __restrict__ out)
{
    __shared__ float tb[32][33];
    const int k0 = blockIdx.x * 32, n0 = blockIdx.y * 32;
    const int tx = threadIdx.x, ty = threadIdx.y;
#pragma unroll
    for (int i = 0; i < 32; i += 8) {
        int k = k0 + ty + i, n = n0 + tx;
        tb[ty + i][tx] = (k < K && n < N) ? in[(size_t)k * N + n] : 0.f;
    }
    __syncthreads();
#pragma unroll
    for (int i = 0; i < 32; i += 8)
        out[(size_t)(n0 + ty + i) * Kpad + k0 + tx] = __float2half_rn(tb[tx][ty + i]);
}

__global__ void wof_kernel(const float* __restrict__ in, __half* __restrict__ out) {
    size_t i = (size_t)blockIdx.x * blockDim.x + threadIdx.x;
    if (i < (size_t)DD * DD) out[i] = __float2half_rn(in[i]);
}

__global__ void rope_q_kernel(const float* __restrict__ qraw, __half* __restrict__ qout) {
    int bs = blockIdx.x;
    int s = bs & (SS - 1), b = bs >> 11;
    for (int i = threadIdx.x; i < DD; i += 256) {
        int hh = i >> 7, d = i & 127;
        const float* src = qraw + (size_t)bs * DD + hh * 128;
        float v;
        if (d < 64) {
            v = src[d];
        } else {
            int dd = d - 64;
            int j = dd & 31;
            float t = (float)s * g_freqs[j];
            float x = src[64 + dd];
            float rx = (dd < 32) ? -src[64 + dd + 32] : src[64 + dd - 32];
            v = x * cosf(t) + rx * sinf(t);
        }
        qout[(((size_t)b * HH + hh) * SS + s) * 128 + d] = __float2half_rn(v);
    }
}

__global__ void reorder_kv_kernel(const float* __restrict__ kvraw, const float* __restrict__ ckv,
                                  __half* __restrict__ kout, __half* __restrict__ vout) {
    __shared__ float kr[64];
    int bs = blockIdx.x;
    int s = bs & (SS - 1), b = bs >> 11;
    int tid = threadIdx.x;
    if (tid < 64) {
        int dd = tid, j = dd & 31;
        float t = (float)s * g_freqs[j];
        const float* src = ckv + (size_t)bs * CKVN + KVPd;
        float x = src[dd];
        float rx = (dd < 32) ? -src[dd + 32] : src[dd - 32];
        kr[dd] = x * cosf(t) + rx * sinf(t);
    }
    __syncthreads();
    for (int i = tid; i < HH * 192; i += 256) {
        int hh = i / 192, d = i % 192;
        __half v = __float2half_rn(kvraw[(size_t)bs * 3072 + i]);
        size_t base = (((size_t)b * HH + hh) * SS + s) * 128;
        if (d < 64) kout[base + d] = v;
        else vout[base + (d - 64)] = v;
    }
    for (int i = tid; i < HH * 64; i += 256) {
        int hh = i >> 6, dd = i & 63;
        kout[(((size_t)b * HH + hh) * SS + s) * 128 + 64 + dd] = __float2half_rn(kr[dd]);
    }
}

// V [bh][s][128] -> Vt [bh][d][s]  (32x32 tiled transpose)
__global__ void vtrans_kernel(const __half* __restrict__ in, __half* __restrict__ out) {
    __shared__ __half tb[32][33];
    const int bh = blockIdx.z;
    const int d0 = blockIdx.x * 32, s0 = blockIdx.y * 32;
    const __half* ib = in + (size_t)bh * SS * 128;
    __half* ob = out + (size_t)bh * 128 * SS;
    const int tx = threadIdx.x, ty = threadIdx.y;
#pragma unroll
    for (int i = 0; i < 32; i += 8)
        tb[ty + i][tx] = ib[(size_t)(s0 + ty + i) * 128 + d0 + tx];
    __syncthreads();
#pragma unroll
    for (int i = 0; i < 32; i += 8)
        ob[(size_t)(d0 + ty + i) * SS + s0 + tx] = tb[tx][ty + i];
}

// ================= attention (all f16 mma), outputs f16 =================
#define QSTRh 136
#define VSTRh 40
#define PSTRh 40
#define ATTN_SMEM ((64 * QSTRh + 32 * QSTRh + 128 * VSTRh + 4 * 16 * PSTRh) * 2)

__global__ __launch_bounds__(128) void attn_kernel(
    const __half* __restrict__ Q, const __half* __restrict__ Kk,
    const __half* __restrict__ Vt, __half* __restrict__ O)
{
    extern __shared__ __half smh[];
    __half* qs = smh;                    // [64][136]
    __half* ks = qs + 64 * QSTRh;        // [32][136]
    __half* vs = ks + 32 * QSTRh;        // [128][40]  (d-major, kv contiguous)
    __half* ps = vs + 128 * VSTRh;       // [4][16][40]
    const int qb = blockIdx.x, bh = blockIdx.y;
    const int b = bh >> 4, h = bh & 15;
    const int tid = threadIdx.x, lane = tid & 31, w = tid >> 5;
    const int g = lane >> 2, t = lane & 3;
    const int rb = w * 16;

    const __half* Qb = Q + ((size_t)bh * SS + qb * 64) * 128;
    const __half* Kb = Kk + (size_t)bh * SS * 128;
    const __half* Vb = Vt + (size_t)bh * 128 * SS;

#pragma unroll
    for (int i = 0; i < 8; i++) {
        int idx = i * 128 + tid;
        int r = idx >> 4, ss = idx & 15;
        cp16(qs + r * QSTRh + ss * 8, Qb + r * 128 + ss * 8);
    }
    asm volatile("cp.async.commit_group;");
    asm volatile("cp.async.wait_group 0;");
    __syncthreads();

    float m_[2] = {-1e30f, -1e30f};
    float l_[2] = {0.f, 0.f};
    float o[16][4];
#pragma unroll
    for (int i = 0; i < 16; i++)
#pragma unroll
        for (int c = 0; c < 4; c++) o[i][c] = 0.f;

    const int nkt = qb * 2 + 2;
    const float scale = 0.08838834764831845f;
    __half* pw = ps + w * 16 * PSTRh;

    // Q fragments are loop-invariant: preload all 8 k-slabs
    uint32_t af[8][4];
#pragma unroll
    for (int k8 = 0; k8 < 8; k8++) {
        const int kb = k8 * 16 + 2 * t;
        af[k8][0] = *(const uint32_t*)(qs + (rb + g) * QSTRh + kb);
        af[k8][1] = *(const uint32_t*)(qs + (rb + g + 8) * QSTRh + kb);
        af[k8][2] = *(const uint32_t*)(qs + (rb + g) * QSTRh + kb + 8);
        af[k8][3] = *(const uint32_t*)(qs + (rb + g + 8) * QSTRh + kb + 8);
    }

    for (int kt = 0; kt < nkt; kt++) {
        // K tile [32][128] and V^T tile [128][32]
#pragma unroll
        for (int i = 0; i < 4; i++) {
            int idx = i * 128 + tid;
            int r = idx >> 4, ss = idx & 15;
            cp16(ks + r * QSTRh + ss * 8, Kb + (size_t)(kt * 32 + r) * 128 + ss * 8);
        }
#pragma unroll
        for (int i = 0; i < 4; i++) {
            int idx = i * 128 + tid;
            int d = idx >> 2, ss = idx & 3;
            cp16(vs + d * VSTRh + ss * 8, Vb + (size_t)d * SS + kt * 32 + ss * 8);
        }
        asm volatile("cp.async.commit_group;");
        asm volatile("cp.async.wait_group 0;");
        __syncthreads();

        // scores: chained f16 over 8 k-slabs, promote once
        float s[4][4];
#pragma unroll
        for (int nt = 0; nt < 4; nt++) {
            uint32_t d0 = 0u, d1 = 0u;
#pragma unroll
            for (int k8 = 0; k8 < 8; k8++) {
                const int kb = k8 * 16 + 2 * t;
                uint32_t b0 = *(const uint32_t*)(ks + (nt * 8 + g) * QSTRh + kb);
                uint32_t b1 = *(const uint32_t*)(ks + (nt * 8 + g) * QSTRh + kb + 8);
                mma_h(d0, d1, af[k8], b0, b1, d0, d1);
            }
            float2 p0 = __half22float2(*reinterpret_cast<__half2*>(&d0));
            float2 p1 = __half22float2(*reinterpret_cast<__half2*>(&d1));
            s[nt][0] = p0.x; s[nt][1] = p0.y; s[nt][2] = p1.x; s[nt][3] = p1.y;
        }

        const int qrow0 = qb * 64 + w * 16 + g;
        const int qrow1 = qrow0 + 8;
#pragma unroll
        for (int nt = 0; nt < 4; nt++)
#pragma unroll
            for (int c = 0; c < 4; c++) {
                int row = (c < 2) ? qrow0 : qrow1;
                int kidx = kt * 32 + nt * 8 + 2 * t + (c & 1);
                float v = s[nt][c] * scale;
                if (kidx > row) v = -1e30f;
                s[nt][c] = v;
            }

        float mx0 = -1e30f, mx1 = -1e30f;
#pragma unroll
        for (int nt = 0; nt < 4; nt++) {
            mx0 = fmaxf(mx0, fmaxf(s[nt][0], s[nt][1]));
            mx1 = fmaxf(mx1, fmaxf(s[nt][2], s[nt][3]));
        }
#pragma unroll
        for (int off = 1; off < 4; off <<= 1) {
            mx0 = fmaxf(mx0, __shfl_xor_sync(0xffffffffu, mx0, off));
            mx1 = fmaxf(mx1, __shfl_xor_sync(0xffffffffu, mx1, off));
        }
        float mn0 = fmaxf(m_[0], mx0), mn1 = fmaxf(m_[1], mx1);
        float al0 = expf(m_[0] - mn0), al1 = expf(m_[1] - mn1);
        float rs0 = 0.f, rs1 = 0.f;
#pragma unroll
        for (int nt = 0; nt < 4; nt++) {
            s[nt][0] = expf(s[nt][0] - mn0);
            s[nt][1] = expf(s[nt][1] - mn0);
            s[nt][2] = expf(s[nt][2] - mn1);
            s[nt][3] = expf(s[nt][3] - mn1);
            rs0 += s[nt][0] + s[nt][1];
            rs1 += s[nt][2] + s[nt][3];
        }
#pragma unroll
        for (int off = 1; off < 4; off <<= 1) {
            rs0 += __shfl_xor_sync(0xffffffffu, rs0, off);
            rs1 += __shfl_xor_sync(0xffffffffu, rs1, off);
        }
        l_[0] = l_[0] * al0 + rs0;
        l_[1] = l_[1] * al1 + rs1;
        m_[0] = mn0; m_[1] = mn1;
#pragma unroll
        for (int nt = 0; nt < 16; nt++) {
            o[nt][0] *= al0; o[nt][1] *= al0;
            o[nt][2] *= al1; o[nt][3] *= al1;
        }

        // stage P as f16 (C layout -> A layout), pairs are contiguous
#pragma unroll
        for (int nt = 0; nt < 4; nt++) {
            *reinterpret_cast<__half2*>(pw + g * PSTRh + nt * 8 + 2 * t) =
                __floats2half2_rn(s[nt][0], s[nt][1]);
            *reinterpret_cast<__half2*>(pw + (g + 8) * PSTRh + nt * 8 + 2 * t) =
                __floats2half2_rn(s[nt][2], s[nt][3]);
        }
        __syncwarp();

        // o += P(16x32) @ V(32x128): 2 chained f16 slabs, promote once per nt
        uint32_t pf[2][4];
#pragma unroll
        for (int ks2 = 0; ks2 < 2; ks2++) {
            const int kb = ks2 * 16 + 2 * t;
            pf[ks2][0] = *(const uint32_t*)(pw + g * PSTRh + kb);
            pf[ks2][1] = *(const uint32_t*)(pw + (g + 8) * PSTRh + kb);
            pf[ks2][2] = *(const uint32_t*)(pw + g * PSTRh + kb + 8);
            pf[ks2][3] = *(const uint32_t*)(pw + (g + 8) * PSTRh + kb + 8);
        }
#pragma unroll
        for (int nt = 0; nt < 16; nt++) {
            const int col = nt * 8 + g;
            uint32_t b00 = *(const uint32_t*)(vs + col * VSTRh + 2 * t);
            uint32_t b01 = *(const uint32_t*)(vs + col * VSTRh + 2 * t + 8);
            uint32_t b10 = *(const uint32_t*)(vs + col * VSTRh + 16 + 2 * t);
            uint32_t b11 = *(const uint32_t*)(vs + col * VSTRh + 16 + 2 * t + 8);
            uint32_t d0, d1, e0, e1;
            mma_h(d0, d1, pf[0], b00, b01, 0u, 0u);
            mma_h(e0, e1, pf[1], b10, b11, d0, d1);
            float2 p0 = __half22float2(*reinterpret_cast<__half2*>(&e0));
            float2 p1 = __half22float2(*reinterpret_cast<__half2*>(&e1));
            o[nt][0] += p0.x;
            o[nt][1] += p0.y;
            o[nt][2] += p1.x;
            o[nt][3] += p1.y;
        }
        __syncwarp();
        __syncthreads();
    }

    float inv0 = 1.f / l_[0], inv1 = 1.f / l_[1];
    const size_t gr0 = (size_t)b * SS + qb * 64 + w * 16 + g;
#pragma unroll
    for (int nt = 0; nt < 16; nt++) {
        int col = h * 128 + nt * 8 + 2 * t;
        O[gr0 * DD + col] = __float2half_rn(o[nt][0] * inv0);
        O[gr0 * DD + col + 1] = __float2half_rn(o[nt][1] * inv0);
        O[(gr0 + 8) * DD + col] = __float2half_rn(o[nt][2] * inv1);
        O[(gr0 + 8) * DD + col + 1] = __float2half_rn(o[nt][3] * inv1);
    }
}

extern "C" void kernel_launch(void* const* d_in, const int* in_sizes, int n_in,
                              void* d_out, int out_size)
{
    (void)in_sizes; (void)n_in; (void)out_size;
    const float* x    = (const float*)d_in[0];
    const float* anw  = (const float*)d_in[1];
    const float* anb  = (const float*)d_in[2];
    const float* Wdq  = (const float*)d_in[3];
    const float* qlw  = (const float*)d_in[4];
    const float* qlb  = (const float*)d_in[5];
    const float* Wuq  = (const float*)d_in[6];
    const float* Wdkv = (const float*)d_in[7];
    const float* klw  = (const float*)d_in[8];
    const float* klb  = (const float*)d_in[9];
    const float* Wukv = (const float*)d_in[10];
    const float* Wo   = (const float*)d_in[11];
    const float* fnw  = (const float*)d_in[12];
    const float* fnb  = (const float*)d_in[13];
    const float* W1   = (const float*)d_in[14];
    const float* b1   = (const float*)d_in[15];
    const float* W2   = (const float*)d_in[16];
    const float* b2   = (const float*)d_in[17];

    float* out = (float*)d_out;
    float* ckv = out + (size_t)MMr * DD;

    float *pcq, *pqraw, *pkvraw, *px2;
    __half *phf, *pcqf, *pkvlf, *pof, *pff1f, *pqh, *pkh, *pvtmp, *pvT;
    __half *pdqt, *pdkvt, *puqt, *pukvt, *pw1t, *pw2t, *pwof;
    cudaGetSymbolAddress((void**)&pcq, g_cq);
    cudaGetSymbolAddress((void**)&pqraw, g_qraw);
    cudaGetSymbolAddress((void**)&pkvraw, g_kvraw);
    cudaGetSymbolAddress((void**)&px2, g_x2);
    cudaGetSymbolAddress((void**)&phf, g_hf);
    cudaGetSymbolAddress((void**)&pcqf, g_cqf);
    cudaGetSymbolAddress((void**)&pkvlf, g_kvlf);
    cudaGetSymbolAddress((void**)&pof, g_of);
    cudaGetSymbolAddress((void**)&pff1f, g_ff1f);
    cudaGetSymbolAddress((void**)&pqh, g_qh);
    cudaGetSymbolAddress((void**)&pkh, g_kh);
    cudaGetSymbolAddress((void**)&pvtmp, g_vtmp);
    cudaGetSymbolAddress((void**)&pvT, g_vT);
    cudaGetSymbolAddress((void**)&pdqt, g_dqt);
    cudaGetSymbolAddress((void**)&pdkvt, g_dkvt);
    cudaGetSymbolAddress((void**)&puqt, g_uqt);
    cudaGetSymbolAddress((void**)&pukvt, g_ukvt);
    cudaGetSymbolAddress((void**)&pw1t, g_w1t);
    cudaGetSymbolAddress((void**)&pw2t, g_w2t);
    cudaGetSymbolAddress((void**)&pwof, g_wof);

    cudaFuncSetAttribute(gemm_h<0>, cudaFuncAttributeMaxDynamicSharedMemorySize, GEMMH_SMEM);
    cudaFuncSetAttribute(gemm_h<1>, cudaFuncAttributeMaxDynamicSharedMemorySize, GEMMH_SMEM);
    cudaFuncSetAttribute(gemm_h<2>, cudaFuncAttributeMaxDynamicSharedMemorySize, GEMMH_SMEM);
    cudaFuncSetAttribute(attn_kernel, cudaFuncAttributeMaxDynamicSharedMemorySize, ATTN_SMEM);

    dim3 blk(256);
    dim3 t32x8(32, 8);
    freqs_kernel<<<1, 32>>>();
    ln_h_kernel<<<MMr, 256, DD * 4>>>(x, DD, DD, anw, anb, phf, DD, DD);
    tconv_h_kernel<<<dim3(64, 32), t32x8>>>(Wdq, DD, QPd, DD, pdqt);
    tconv_h_kernel<<<dim3(64, 48), t32x8>>>(Wdkv, DD, CKVN, DD, pdkvt);
    tconv_h_kernel<<<dim3(32, 64), t32x8>>>(Wuq, QPd, DD, QPd, puqt);
    tconv_h_kernel<<<dim3(43, 96), t32x8>>>(Wukv, KVPd, 3072, KVL_PAD, pukvt);
    tconv_h_kernel<<<dim3(64, 256), t32x8>>>(W1, DD, FFd, DD, pw1t);
    tconv_h_kernel<<<dim3(256, 64), t32x8>>>(W2, FFd, DD, FFd, pw2t);
    wof_kernel<<<(DD * DD + 255) / 256, 256>>>(Wo, pwof);

    // cq_raw = h @ W_dq
    gemm_h<0><<<dim3(QPd / 128, MMr / 128), blk, GEMMH_SMEM>>>(
        phf, DD, pdqt, DD, pcq, nullptr, QPd, QPd, DD, nullptr, nullptr, 0);
    // ckv = h @ W_dkv (N=1429 guarded)
    gemm_h<0><<<dim3(DKV_NPAD / 128, MMr / 128), blk, GEMMH_SMEM>>>(
        phf, DD, pdkvt, DD, ckv, nullptr, CKVN, CKVN, DD, nullptr, nullptr, 0);
    ln_h_kernel<<<MMr, 256, QPd * 4>>>(pcq, QPd, QPd, qlw, qlb, pcqf, QPd, QPd);
    ln_h_kernel<<<MMr, 256, KVPd * 4>>>(ckv, CKVN, KVPd, klw, klb, pkvlf, KVL_PAD, KVL_PAD);
    // Q_raw = cq @ W_uq
    gemm_h<0><<<dim3(DD / 128, MMr / 128), blk, GEMMH_SMEM>>>(
        pcqf, QPd, puqt, QPd, pqraw, nullptr, DD, DD, QPd, nullptr, nullptr, 0);
    // KV_raw = kv_lora @ W_ukv
    gemm_h<0><<<dim3(3072 / 128, MMr / 128), blk, GEMMH_SMEM>>>(
        pkvlf, KVL_PAD, pukvt, KVL_PAD, pkvraw, nullptr, 3072, 3072, KVL_PAD, nullptr, nullptr, 0);

    rope_q_kernel<<<MMr, 256>>>(pqraw, pqh);
    reorder_kv_kernel<<<MMr, 256>>>(pkvraw, ckv, pkh, pvtmp);
    vtrans_kernel<<<dim3(4, 64, BB * HH), t32x8>>>(pvtmp, pvT);
    attn_kernel<<<dim3(SS / 64, BB * HH), 128, ATTN_SMEM>>>(pqh, pkh, pvT, pof);

    // x2 = x + o @ Wo^T
    gemm_h<2><<<dim3(DD / 128, MMr / 128), blk, GEMMH_SMEM>>>(
        pof, DD, pwof, DD, px2, nullptr, DD, DD, DD, nullptr, x, DD);
    ln_h_kernel<<<MMr, 256, DD * 4>>>(px2, DD, DD, fnw, fnb, phf, DD, DD);
    // ff1 = gelu(h @ W1 + b1) -> f16
    gemm_h<1><<<dim3(FFd / 128, MMr / 128), blk, GEMMH_SMEM>>>(
        phf, DD, pw1t, DD, nullptr, pff1f, FFd, FFd, DD, b1, nullptr, 0);
    // out = x2 + ff1 @ W2 + b2
    gemm_h<2><<<dim3(DD / 128, MMr / 128), blk, GEMMH_SMEM>>>(
        pff1f, FFd, pw2t, FFd, out, nullptr, DD, DD, FFd, b2, px2, DD);
}

// round 15
// speedup vs baseline: 2.1234x; 1.0697x over previous
#include <cuda_runtime.h>
#include <cuda_fp16.h>
#include <math.h>
#include <stdint.h>

#define BB 2
#define SS 2048
#define DD 2048
#define HH 16
#define QPd 1024
#define KVPd 1365
#define CKVN 1429
#define FFd 8192
#define MMr 4096
#define KVL_PAD 1408
#define DKV_NPAD 1536

// fp32 scratch
__device__ float g_cq[(size_t)MMr * QPd];
__device__ float g_qraw[(size_t)MMr * DD];
__device__ float g_kvraw[(size_t)MMr * 3072];
__device__ float g_x2[(size_t)MMr * DD];
__device__ float g_freqs[32];
// f16 activations
__device__ __half g_hf[(size_t)MMr * DD];
__device__ __half g_cqf[(size_t)MMr * QPd];
__device__ __half g_kvlf[(size_t)MMr * KVL_PAD];
__device__ __half g_of[(size_t)MMr * DD];
__device__ __half g_ff1f[(size_t)MMr * FFd];
__device__ __half g_qh[(size_t)MMr * DD];
__device__ __half g_kh[(size_t)MMr * DD];
__device__ __half g_vtmp[(size_t)MMr * DD];
__device__ __half g_vT[(size_t)MMr * DD];
// f16 weights [N,K]
__device__ __half g_dqt[(size_t)QPd * DD];
__device__ __half g_dkvt[(size_t)DKV_NPAD * DD];
__device__ __half g_uqt[(size_t)DD * QPd];
__device__ __half g_ukvt[(size_t)3072 * KVL_PAD];
__device__ __half g_w1t[(size_t)FFd * DD];
__device__ __half g_w2t[(size_t)DD * FFd];
__device__ __half g_wof[(size_t)DD * DD];

__device__ __forceinline__ void mma_h(uint32_t& d0, uint32_t& d1, const uint32_t* a,
                                      uint32_t b0, uint32_t b1, uint32_t c0, uint32_t c1) {
    asm volatile(
        "mma.sync.aligned.m16n8k16.row.col.f16.f16.f16.f16 "
        "{%0,%1}, {%2,%3,%4,%5}, {%6,%7}, {%8,%9};"
        : "=r"(d0), "=r"(d1)
        : "r"(a[0]), "r"(a[1]), "r"(a[2]), "r"(a[3]), "r"(b0), "r"(b1), "r"(c0), "r"(c1));
}
__device__ __forceinline__ void cp16(void* dst, const void* src) {
    uint32_t d = (uint32_t)__cvta_generic_to_shared(dst);
    asm volatile("cp.async.cg.shared.global [%0], [%1], 16;" :: "r"(d), "l"(src));
}

// ================= f16 GEMM: C[M,N] = A[M,K] @ B[N,K]^T =================
// CTA 128x128, 8 warps (4x2), warp tile 32x64. K-slab 64, 4-deep f16 chains.
#define HSTR 72
#define HT_ELE (128 * HSTR)
#define GEMMH_SMEM (4 * HT_ELE * 2)  // 2 tiles x 2 buffers x 2B = 73728

// EPI: 0 fp32 out ; 1 bias+GELU -> f16 out ; 2 (opt bias)+residual -> fp32 out
template <int EPI>
__global__ __launch_bounds__(256) void gemm_h(
    const __half* __restrict__ A, int lda,
    const __half* __restrict__ B, int ldb,
    float* __restrict__ C, __half* __restrict__ Ch, int ldc,
    int N, int K,
    const float* __restrict__ bias, const float* __restrict__ res, int ldres)
{
    extern __shared__ __half smh[];
    __half* As = smh;
    __half* Bs = smh + 2 * HT_ELE;
    const int tid = threadIdx.x, lane = tid & 31, warp = tid >> 5;
    const int wm = warp >> 1, wn = warp & 1;
    const int bm0 = blockIdx.y * 128, bn0 = blockIdx.x * 128;
    const int g = lane >> 2, t = lane & 3;

    float acc[2][8][4];
#pragma unroll
    for (int i = 0; i < 2; i++)
#pragma unroll
        for (int j = 0; j < 8; j++)
#pragma unroll
            for (int c = 0; c < 4; c++) acc[i][j][c] = 0.f;

    const int KT = K / 64;
    auto load_tiles = [&](int buf, int k0) {
        __half* Ab = As + buf * HT_ELE;
        __half* Bb = Bs + buf * HT_ELE;
#pragma unroll
        for (int i = 0; i < 4; i++) {
            int idx = i * 256 + tid;
            int r = idx >> 3, s = idx & 7;
            cp16(Ab + r * HSTR + s * 8, A + (size_t)(bm0 + r) * lda + k0 + s * 8);
        }
#pragma unroll
        for (int i = 0; i < 4; i++) {
            int idx = i * 256 + tid;
            int r = idx >> 3, s = idx & 7;
            cp16(Bb + r * HSTR + s * 8, B + (size_t)(bn0 + r) * ldb + k0 + s * 8);
        }
        asm volatile("cp.async.commit_group;");
    };

    load_tiles(0, 0);
    int buf = 0;
    for (int kt = 0; kt < KT; kt++) {
        if (kt + 1 < KT) {
            load_tiles(buf ^ 1, (kt + 1) * 64);
            asm volatile("cp.async.wait_group 1;");
        } else {
            asm volatile("cp.async.wait_group 0;");
        }
        __syncthreads();
        const __half* Ab = As + buf * HT_ELE;
        const __half* Bb = Bs + buf * HT_ELE;

        // preload all 4 k16-slabs of A fragments
        uint32_t af[4][2][4];
#pragma unroll
        for (int ks = 0; ks < 4; ks++) {
            const int kb = ks * 16 + 2 * t;
#pragma unroll
            for (int im = 0; im < 2; im++) {
                const int r = wm * 32 + im * 16 + g;
                af[ks][im][0] = *(const uint32_t*)(Ab + r * HSTR + kb);
                af[ks][im][1] = *(const uint32_t*)(Ab + (r + 8) * HSTR + kb);
                af[ks][im][2] = *(const uint32_t*)(Ab + r * HSTR + kb + 8);
                af[ks][im][3] = *(const uint32_t*)(Ab + (r + 8) * HSTR + kb + 8);
            }
        }
#pragma unroll
        for (int nt = 0; nt < 8; nt++) {
            const int c = wn * 64 + nt * 8 + g;
            uint32_t bf[4][2];
#pragma unroll
            for (int ks = 0; ks < 4; ks++) {
                const int kb = ks * 16 + 2 * t;
                bf[ks][0] = *(const uint32_t*)(Bb + c * HSTR + kb);
                bf[ks][1] = *(const uint32_t*)(Bb + c * HSTR + kb + 8);
            }
#pragma unroll
            for (int im = 0; im < 2; im++) {
                uint32_t d0 = 0u, d1 = 0u;
#pragma unroll
                for (int ks = 0; ks < 4; ks++)
                    mma_h(d0, d1, af[ks][im], bf[ks][0], bf[ks][1], d0, d1);
                float2 p0 = __half22float2(*reinterpret_cast<__half2*>(&d0));
                float2 p1 = __half22float2(*reinterpret_cast<__half2*>(&d1));
                acc[im][nt][0] += p0.x;
                acc[im][nt][1] += p0.y;
                acc[im][nt][2] += p1.x;
                acc[im][nt][3] += p1.y;
            }
        }
        __syncthreads();
        buf ^= 1;
    }
#pragma unroll
    for (int im = 0; im < 2; im++)
#pragma unroll
        for (int nt = 0; nt < 8; nt++) {
            const int r0 = bm0 + wm * 32 + im * 16 + g;
            const int c0 = bn0 + wn * 64 + nt * 8 + 2 * t;
#pragma unroll
            for (int e = 0; e < 4; e++) {
                int r = r0 + (e >> 1) * 8;
                int c = c0 + (e & 1);
                if (c < N) {
                    float v = acc[im][nt][e];
                    if (EPI == 0) {
                        C[(size_t)r * ldc + c] = v;
                    } else if (EPI == 1) {
                        v += bias[c];
                        v = 0.5f * v * (1.f + erff(v * 0.7071067811865475f));
                        Ch[(size_t)r * ldc + c] = __float2half_rn(v);
                    } else {
                        if (bias) v += bias[c];
                        v += res[(size_t)r * ldres + c];
                        C[(size_t)r * ldc + c] = v;
                    }
                }
            }
        }
}

// ================= LayerNorm -> f16 =================
__global__ void ln_h_kernel(const float* __restrict__ in, int ldin, int cols,
                            const float* __restrict__ w, const float* __restrict__ b,
                            __half* __restrict__ out, int ldout, int padto)
{
    extern __shared__ float sbuf[];
    __shared__ float red[8];
    __shared__ float bc[2];
    const int row = blockIdx.x, tid = threadIdx.x, lane = tid & 31, warp = tid >> 5;
    const float* ip = in + (size_t)row * ldin;
    float s = 0.f;
    for (int c = tid; c < cols; c += 256) { float v = ip[c]; sbuf[c] = v; s += v; }
#pragma unroll
    for (int o = 16; o > 0; o >>= 1) s += __shfl_xor_sync(0xffffffffu, s, o);
    if (lane == 0) red[warp] = s;
    __syncthreads();
    if (tid == 0) { float t = 0; for (int i = 0; i < 8; i++) t += red[i]; bc[0] = t / cols; }
    __syncthreads();
    float mean = bc[0], vs = 0.f;
    for (int c = tid; c < cols; c += 256) { float d = sbuf[c] - mean; vs += d * d; }
#pragma unroll
    for (int o = 16; o > 0; o >>= 1) vs += __shfl_xor_sync(0xffffffffu, vs, o);
    if (lane == 0) red[warp] = vs;
    __syncthreads();
    if (tid == 0) { float t = 0; for (int i = 0; i < 8; i++) t += red[i]; bc[1] = rsqrtf(t / cols + 1e-5f); }
    __syncthreads();
    float inv = bc[1];
    __half* op = out + (size_t)row * ldout;
    for (int c = tid; c < cols; c += 256) op[c] = __float2half_rn((sbuf[c] - mean) * inv * w[c] + b[c]);
    for (int c = cols + tid; c < padto; c += 256) op[c] = __float2half_rn(0.f);
}

__global__ void freqs_kernel() {
    int j = threadIdx.x;
    if (j < 32) g_freqs[j] = (float)exp(-(double)j * 0.14391156831212787);
}

// [K,N] fp32 -> [Npad,Kpad] f16 transpose-convert, zero-padded. Grid: (Kpad/32, Npad/32)
__global__ void tconv_h_kernel(const float* __restrict__ in, int K, int N, int Kpad,
                               __half* __restrict__ out)
{
    __shared__ float tb[32][33];
    const int k0 = blockIdx.x * 32, n0 = blockIdx.y * 32;
    const int tx = threadIdx.x, ty = threadIdx.y;
#pragma unroll
    for (int i = 0; i < 32; i += 8) {
        int k = k0 + ty + i, n = n0 + tx;
        tb[ty + i][tx] = (k < K && n < N) ? in[(size_t)k * N + n] : 0.f;
    }
    __syncthreads();
#pragma unroll
    for (int i = 0; i < 32; i += 8)
        out[(size_t)(n0 + ty + i) * Kpad + k0 + tx] = __float2half_rn(tb[tx][ty + i]);
}

__global__ void wof_kernel(const float* __restrict__ in, __half* __restrict__ out) {
    size_t i = (size_t)blockIdx.x * blockDim.x + threadIdx.x;
    if (i < (size_t)DD * DD) out[i] = __float2half_rn(in[i]);
}

__global__ void rope_q_kernel(const float* __restrict__ qraw, __half* __restrict__ qout) {
    int bs = blockIdx.x;
    int s = bs & (SS - 1), b = bs >> 11;
    for (int i = threadIdx.x; i < DD; i += 256) {
        int hh = i >> 7, d = i & 127;
        const float* src = qraw + (size_t)bs * DD + hh * 128;
        float v;
        if (d < 64) {
            v = src[d];
        } else {
            int dd = d - 64;
            int j = dd & 31;
            float t = (float)s * g_freqs[j];
            float x = src[64 + dd];
            float rx = (dd < 32) ? -src[64 + dd + 32] : src[64 + dd - 32];
            v = x * cosf(t) + rx * sinf(t);
        }
        qout[(((size_t)b * HH + hh) * SS + s) * 128 + d] = __float2half_rn(v);
    }
}

__global__ void reorder_kv_kernel(const float* __restrict__ kvraw, const float* __restrict__ ckv,
                                  __half* __restrict__ kout, __half* __restrict__ vout) {
    __shared__ float kr[64];
    int bs = blockIdx.x;
    int s = bs & (SS - 1), b = bs >> 11;
    int tid = threadIdx.x;
    if (tid < 64) {
        int dd = tid, j = dd & 31;
        float t = (float)s * g_freqs[j];
        const float* src = ckv + (size_t)bs * CKVN + KVPd;
        float x = src[dd];
        float rx = (dd < 32) ? -src[dd + 32] : src[dd - 32];
        kr[dd] = x * cosf(t) + rx * sinf(t);
    }
    __syncthreads();
    for (int i = tid; i < HH * 192; i += 256) {
        int hh = i / 192, d = i % 192;
        __half v = __float2half_rn(kvraw[(size_t)bs * 3072 + i]);
        size_t base = (((size_t)b * HH + hh) * SS + s) * 128;
        if (d < 64) kout[base + d] = v;
        else vout[base + (d - 64)] = v;
    }
    for (int i = tid; i < HH * 64; i += 256) {
        int hh = i >> 6, dd = i & 63;
        kout[(((size_t)b * HH + hh) * SS + s) * 128 + 64 + dd] = __float2half_rn(kr[dd]);
    }
}

// V [bh][s][128] -> Vt [bh][d][s]
__global__ void vtrans_kernel(const __half* __restrict__ in, __half* __restrict__ out) {
    __shared__ __half tb[32][33];
    const int bh = blockIdx.z;
    const int d0 = blockIdx.x * 32, s0 = blockIdx.y * 32;
    const __half* ib = in + (size_t)bh * SS * 128;
    __half* ob = out + (size_t)bh * 128 * SS;
    const int tx = threadIdx.x, ty = threadIdx.y;
#pragma unroll
    for (int i = 0; i < 32; i += 8)
        tb[ty + i][tx] = ib[(size_t)(s0 + ty + i) * 128 + d0 + tx];
    __syncthreads();
#pragma unroll
    for (int i = 0; i < 32; i += 8)
        ob[(size_t)(d0 + ty + i) * SS + s0 + tx] = tb[tx][ty + i];
}

// ================= attention (all f16 mma), outputs f16 =================
#define QSTRh 136
#define VSTRh 40
#define PSTRh 40
#define ATTN_SMEM ((64 * QSTRh + 32 * QSTRh + 128 * VSTRh + 4 * 16 * PSTRh) * 2)

__global__ __launch_bounds__(128) void attn_kernel(
    const __half* __restrict__ Q, const __half* __restrict__ Kk,
    const __half* __restrict__ Vt, __half* __restrict__ O)
{
    extern __shared__ __half smh[];
    __half* qs = smh;
    __half* ks = qs + 64 * QSTRh;
    __half* vs = ks + 32 * QSTRh;
    __half* ps = vs + 128 * VSTRh;
    const int qb = blockIdx.x, bh = blockIdx.y;
    const int b = bh >> 4, h = bh & 15;
    const int tid = threadIdx.x, lane = tid & 31, w = tid >> 5;
    const int g = lane >> 2, t = lane & 3;
    const int rb = w * 16;

    const __half* Qb = Q + ((size_t)bh * SS + qb * 64) * 128;
    const __half* Kb = Kk + (size_t)bh * SS * 128;
    const __half* Vb = Vt + (size_t)bh * 128 * SS;

#pragma unroll
    for (int i = 0; i < 8; i++) {
        int idx = i * 128 + tid;
        int r = idx >> 4, ss = idx & 15;
        cp16(qs + r * QSTRh + ss * 8, Qb + r * 128 + ss * 8);
    }
    asm volatile("cp.async.commit_group;");
    asm volatile("cp.async.wait_group 0;");
    __syncthreads();

    float m_[2] = {-1e30f, -1e30f};
    float l_[2] = {0.f, 0.f};
    float o[16][4];
#pragma unroll
    for (int i = 0; i < 16; i++)
#pragma unroll
        for (int c = 0; c < 4; c++) o[i][c] = 0.f;

    const int nkt = qb * 2 + 2;
    const float scale = 0.08838834764831845f;
    __half* pw = ps + w * 16 * PSTRh;

    uint32_t af[8][4];
#pragma unroll
    for (int k8 = 0; k8 < 8; k8++) {
        const int kb = k8 * 16 + 2 * t;
        af[k8][0] = *(const uint32_t*)(qs + (rb + g) * QSTRh + kb);
        af[k8][1] = *(const uint32_t*)(qs + (rb + g + 8) * QSTRh + kb);
        af[k8][2] = *(const uint32_t*)(qs + (rb + g) * QSTRh + kb + 8);
        af[k8][3] = *(const uint32_t*)(qs + (rb + g + 8) * QSTRh + kb + 8);
    }

    for (int kt = 0; kt < nkt; kt++) {
#pragma unroll
        for (int i = 0; i < 4; i++) {
            int idx = i * 128 + tid;
            int r = idx >> 4, ss = idx & 15;
            cp16(ks + r * QSTRh + ss * 8, Kb + (size_t)(kt * 32 + r) * 128 + ss * 8);
        }
#pragma unroll
        for (int i = 0; i < 4; i++) {
            int idx = i * 128 + tid;
            int d = idx >> 2, ss = idx & 3;
            cp16(vs + d * VSTRh + ss * 8, Vb + (size_t)d * SS + kt * 32 + ss * 8);
        }
        asm volatile("cp.async.commit_group;");
        asm volatile("cp.async.wait_group 0;");
        __syncthreads();

        float s[4][4];
#pragma unroll
        for (int nt = 0; nt < 4; nt++) {
            uint32_t d0 = 0u, d1 = 0u;
#pragma unroll
            for (int k8 = 0; k8 < 8; k8++) {
                const int kb = k8 * 16 + 2 * t;
                uint32_t b0 = *(const uint32_t*)(ks + (nt * 8 + g) * QSTRh + kb);
                uint32_t b1 = *(const uint32_t*)(ks + (nt * 8 + g) * QSTRh + kb + 8);
                mma_h(d0, d1, af[k8], b0, b1, d0, d1);
            }
            float2 p0 = __half22float2(*reinterpret_cast<__half2*>(&d0));
            float2 p1 = __half22float2(*reinterpret_cast<__half2*>(&d1));
            s[nt][0] = p0.x; s[nt][1] = p0.y; s[nt][2] = p1.x; s[nt][3] = p1.y;
        }

        const int qrow0 = qb * 64 + w * 16 + g;
        const int qrow1 = qrow0 + 8;
#pragma unroll
        for (int nt = 0; nt < 4; nt++)
#pragma unroll
            for (int c = 0; c < 4; c++) {
                int row = (c < 2) ? qrow0 : qrow1;
                int kidx = kt * 32 + nt * 8 + 2 * t + (c & 1);
                float v = s[nt][c] * scale;
                if (kidx > row) v = -1e30f;
                s[nt][c] = v;
            }

        float mx0 = -1e30f, mx1 = -1e30f;
#pragma unroll
        for (int nt = 0; nt < 4; nt++) {
            mx0 = fmaxf(mx0, fmaxf(s[nt][0], s[nt][1]));
            mx1 = fmaxf(mx1, fmaxf(s[nt][2], s[nt][3]));
        }
#pragma unroll
        for (int off = 1; off < 4; off <<= 1) {
            mx0 = fmaxf(mx0, __shfl_xor_sync(0xffffffffu, mx0, off));
            mx1 = fmaxf(mx1, __shfl_xor_sync(0xffffffffu, mx1, off));
        }
        float mn0 = fmaxf(m_[0], mx0), mn1 = fmaxf(m_[1], mx1);
        float al0 = expf(m_[0] - mn0), al1 = expf(m_[1] - mn1);
        float rs0 = 0.f, rs1 = 0.f;
#pragma unroll
        for (int nt = 0; nt < 4; nt++) {
            s[nt][0] = expf(s[nt][0] - mn0);
            s[nt][1] = expf(s[nt][1] - mn0);
            s[nt][2] = expf(s[nt][2] - mn1);
            s[nt][3] = expf(s[nt][3] - mn1);
            rs0 += s[nt][0] + s[nt][1];
            rs1 += s[nt][2] + s[nt][3];
        }
#pragma unroll
        for (int off = 1; off < 4; off <<= 1) {
            rs0 += __shfl_xor_sync(0xffffffffu, rs0, off);
            rs1 += __shfl_xor_sync(0xffffffffu, rs1, off);
        }
        l_[0] = l_[0] * al0 + rs0;
        l_[1] = l_[1] * al1 + rs1;
        m_[0] = mn0; m_[1] = mn1;
#pragma unroll
        for (int nt = 0; nt < 16; nt++) {
            o[nt][0] *= al0; o[nt][1] *= al0;
            o[nt][2] *= al1; o[nt][3] *= al1;
        }

#pragma unroll
        for (int nt = 0; nt < 4; nt++) {
            *reinterpret_cast<__half2*>(pw + g * PSTRh + nt * 8 + 2 * t) =
                __floats2half2_rn(s[nt][0], s[nt][1]);
            *reinterpret_cast<__half2*>(pw + (g + 8) * PSTRh + nt * 8 + 2 * t) =
                __floats2half2_rn(s[nt][2], s[nt][3]);
        }
        __syncwarp();

        uint32_t pf[2][4];
#pragma unroll
        for (int ks2 = 0; ks2 < 2; ks2++) {
            const int kb = ks2 * 16 + 2 * t;
            pf[ks2][0] = *(const uint32_t*)(pw + g * PSTRh + kb);
            pf[ks2][1] = *(const uint32_t*)(pw + (g + 8) * PSTRh + kb);
            pf[ks2][2] = *(const uint32_t*)(pw + g * PSTRh + kb + 8);
            pf[ks2][3] = *(const uint32_t*)(pw + (g + 8) * PSTRh + kb + 8);
        }
#pragma unroll
        for (int nt = 0; nt < 16; nt++) {
            const int col = nt * 8 + g;
            uint32_t b00 = *(const uint32_t*)(vs + col * VSTRh + 2 * t);
            uint32_t b01 = *(const uint32_t*)(vs + col * VSTRh + 2 * t + 8);
            uint32_t b10 = *(const uint32_t*)(vs + col * VSTRh + 16 + 2 * t);
            uint32_t b11 = *(const uint32_t*)(vs + col * VSTRh + 16 + 2 * t + 8);
            uint32_t d0, d1, e0, e1;
            mma_h(d0, d1, pf[0], b00, b01, 0u, 0u);
            mma_h(e0, e1, pf[1], b10, b11, d0, d1);
            float2 p0 = __half22float2(*reinterpret_cast<__half2*>(&e0));
            float2 p1 = __half22float2(*reinterpret_cast<__half2*>(&e1));
            o[nt][0] += p0.x;
            o[nt][1] += p0.y;
            o[nt][2] += p1.x;
            o[nt][3] += p1.y;
        }
        __syncwarp();
        __syncthreads();
    }

    float inv0 = 1.f / l_[0], inv1 = 1.f / l_[1];
    const size_t gr0 = (size_t)b * SS + qb * 64 + w * 16 + g;
#pragma unroll
    for (int nt = 0; nt < 16; nt++) {
        int col = h * 128 + nt * 8 + 2 * t;
        O[gr0 * DD + col] = __float2half_rn(o[nt][0] * inv0);
        O[gr0 * DD + col + 1] = __float2half_rn(o[nt][1] * inv0);
        O[(gr0 + 8) * DD + col] = __float2half_rn(o[nt][2] * inv1);
        O[(gr0 + 8) * DD + col + 1] = __float2half_rn(o[nt][3] * inv1);
    }
}

extern "C" void kernel_launch(void* const* d_in, const int* in_sizes, int n_in,
                              void* d_out, int out_size)
{
    (void)in_sizes; (void)n_in; (void)out_size;
    const float* x    = (const float*)d_in[0];
    const float* anw  = (const float*)d_in[1];
    const float* anb  = (const float*)d_in[2];
    const float* Wdq  = (const float*)d_in[3];
    const float* qlw  = (const float*)d_in[4];
    const float* qlb  = (const float*)d_in[5];
    const float* Wuq  = (const float*)d_in[6];
    const float* Wdkv = (const float*)d_in[7];
    const float* klw  = (const float*)d_in[8];
    const float* klb  = (const float*)d_in[9];
    const float* Wukv = (const float*)d_in[10];
    const float* Wo   = (const float*)d_in[11];
    const float* fnw  = (const float*)d_in[12];
    const float* fnb  = (const float*)d_in[13];
    const float* W1   = (const float*)d_in[14];
    const float* b1   = (const float*)d_in[15];
    const float* W2   = (const float*)d_in[16];
    const float* b2   = (const float*)d_in[17];

    float* out = (float*)d_out;
    float* ckv = out + (size_t)MMr * DD;

    float *pcq, *pqraw, *pkvraw, *px2;
    __half *phf, *pcqf, *pkvlf, *pof, *pff1f, *pqh, *pkh, *pvtmp, *pvT;
    __half *pdqt, *pdkvt, *puqt, *pukvt, *pw1t, *pw2t, *pwof;
    cudaGetSymbolAddress((void**)&pcq, g_cq);
    cudaGetSymbolAddress((void**)&pqraw, g_qraw);
    cudaGetSymbolAddress((void**)&pkvraw, g_kvraw);
    cudaGetSymbolAddress((void**)&px2, g_x2);
    cudaGetSymbolAddress((void**)&phf, g_hf);
    cudaGetSymbolAddress((void**)&pcqf, g_cqf);
    cudaGetSymbolAddress((void**)&pkvlf, g_kvlf);
    cudaGetSymbolAddress((void**)&pof, g_of);
    cudaGetSymbolAddress((void**)&pff1f, g_ff1f);
    cudaGetSymbolAddress((void**)&pqh, g_qh);
    cudaGetSymbolAddress((void**)&pkh, g_kh);
    cudaGetSymbolAddress((void**)&pvtmp, g_vtmp);
    cudaGetSymbolAddress((void**)&pvT, g_vT);
    cudaGetSymbolAddress((void**)&pdqt, g_dqt);
    cudaGetSymbolAddress((void**)&pdkvt, g_dkvt);
    cudaGetSymbolAddress((void**)&puqt, g_uqt);
    cudaGetSymbolAddress((void**)&pukvt, g_ukvt);
    cudaGetSymbolAddress((void**)&pw1t, g_w1t);
    cudaGetSymbolAddress((void**)&pw2t, g_w2t);
    cudaGetSymbolAddress((void**)&pwof, g_wof);

    cudaFuncSetAttribute(gemm_h<0>, cudaFuncAttributeMaxDynamicSharedMemorySize, GEMMH_SMEM);
    cudaFuncSetAttribute(gemm_h<1>, cudaFuncAttributeMaxDynamicSharedMemorySize, GEMMH_SMEM);
    cudaFuncSetAttribute(gemm_h<2>, cudaFuncAttributeMaxDynamicSharedMemorySize, GEMMH_SMEM);
    cudaFuncSetAttribute(attn_kernel, cudaFuncAttributeMaxDynamicSharedMemorySize, ATTN_SMEM);

    dim3 blk(256);
    dim3 t32x8(32, 8);
    freqs_kernel<<<1, 32>>>();
    ln_h_kernel<<<MMr, 256, DD * 4>>>(x, DD, DD, anw, anb, phf, DD, DD);
    tconv_h_kernel<<<dim3(64, 32), t32x8>>>(Wdq, DD, QPd, DD, pdqt);
    tconv_h_kernel<<<dim3(64, 48), t32x8>>>(Wdkv, DD, CKVN, DD, pdkvt);
    tconv_h_kernel<<<dim3(32, 64), t32x8>>>(Wuq, QPd, DD, QPd, puqt);
    tconv_h_kernel<<<dim3(44, 96), t32x8>>>(Wukv, KVPd, 3072, KVL_PAD, pukvt);
    tconv_h_kernel<<<dim3(64, 256), t32x8>>>(W1, DD, FFd, DD, pw1t);
    tconv_h_kernel<<<dim3(256, 64), t32x8>>>(W2, FFd, DD, FFd, pw2t);
    wof_kernel<<<(DD * DD + 255) / 256, 256>>>(Wo, pwof);

    // cq_raw = h @ W_dq
    gemm_h<0><<<dim3(QPd / 128, MMr / 128), blk, GEMMH_SMEM>>>(
        phf, DD, pdqt, DD, pcq, nullptr, QPd, QPd, DD, nullptr, nullptr, 0);
    // ckv = h @ W_dkv (N=1429 guarded)
    gemm_h<0><<<dim3(DKV_NPAD / 128, MMr / 128), blk, GEMMH_SMEM>>>(
        phf, DD, pdkvt, DD, ckv, nullptr, CKVN, CKVN, DD, nullptr, nullptr, 0);
    ln_h_kernel<<<MMr, 256, QPd * 4>>>(pcq, QPd, QPd, qlw, qlb, pcqf, QPd, QPd);
    ln_h_kernel<<<MMr, 256, KVPd * 4>>>(ckv, CKVN, KVPd, klw, klb, pkvlf, KVL_PAD, KVL_PAD);
    // Q_raw = cq @ W_uq
    gemm_h<0><<<dim3(DD / 128, MMr / 128), blk, GEMMH_SMEM>>>(
        pcqf, QPd, puqt, QPd, pqraw, nullptr, DD, DD, QPd, nullptr, nullptr, 0);
    // KV_raw = kv_lora @ W_ukv
    gemm_h<0><<<dim3(3072 / 128, MMr / 128), blk, GEMMH_SMEM>>>(
        pkvlf, KVL_PAD, pukvt, KVL_PAD, pkvraw, nullptr, 3072, 3072, KVL_PAD, nullptr, nullptr, 0);

    rope_q_kernel<<<MMr, 256>>>(pqraw, pqh);
    reorder_kv_kernel<<<MMr, 256>>>(pkvraw, ckv, pkh, pvtmp);
    vtrans_kernel<<<dim3(4, 64, BB * HH), t32x8>>>(pvtmp, pvT);
    attn_kernel<<<dim3(SS / 64, BB * HH), 128, ATTN_SMEM>>>(pqh, pkh, pvT, pof);

    // x2 = x + o @ Wo^T
    gemm_h<2><<<dim3(DD / 128, MMr / 128), blk, GEMMH_SMEM>>>(
        pof, DD, pwof, DD, px2, nullptr, DD, DD, DD, nullptr, x, DD);
    ln_h_kernel<<<MMr, 256, DD * 4>>>(px2, DD, DD, fnw, fnb, phf, DD, DD);
    // ff1 = gelu(h @ W1 + b1) -> f16
    gemm_h<1><<<dim3(FFd / 128, MMr / 128), blk, GEMMH_SMEM>>>(
        phf, DD, pw1t, DD, nullptr, pff1f, FFd, FFd, DD, b1, nullptr, 0);
    // out = x2 + ff1 @ W2 + b2
    gemm_h<2><<<dim3(DD / 128, MMr / 128), blk, GEMMH_SMEM>>>(
        pff1f, FFd, pw2t, FFd, out, nullptr, DD, DD, FFd, b2, px2, DD);
}

// round 16
// speedup vs baseline: 2.2939x; 1.0803x over previous
#include <cuda_runtime.h>
#include <cuda_fp16.h>
#include <math.h>
#include <stdint.h>

#define BB 2
#define SS 2048
#define DD 2048
#define HH 16
#define QPd 1024
#define KVPd 1365
#define CKVN 1429
#define FFd 8192
#define MMr 4096
#define KVL_PAD 1408
#define DKV_NPAD 1536

// fp32 scratch
__device__ float g_cq[(size_t)MMr * QPd];
__device__ float g_x2[(size_t)MMr * DD];
__device__ float g_freqs[32];
// f16 activations
__device__ __half g_hf[(size_t)MMr * DD];
__device__ __half g_cqf[(size_t)MMr * QPd];
__device__ __half g_kvlf[(size_t)MMr * KVL_PAD];
__device__ __half g_of[(size_t)MMr * DD];
__device__ __half g_ff1f[(size_t)MMr * FFd];
__device__ __half g_qrawh[(size_t)MMr * DD];
__device__ __half g_kvrawh[(size_t)MMr * 3072];
__device__ __half g_qh[(size_t)MMr * DD];
__device__ __half g_kh[(size_t)MMr * DD];
__device__ __half g_vtmp[(size_t)MMr * DD];
__device__ __half g_vT[(size_t)MMr * DD];
// f16 weights [N,K]
__device__ __half g_dqt[(size_t)QPd * DD];
__device__ __half g_dkvt[(size_t)DKV_NPAD * DD];
__device__ __half g_uqt[(size_t)DD * QPd];
__device__ __half g_ukvt[(size_t)3072 * KVL_PAD];
__device__ __half g_w1t[(size_t)FFd * DD];
__device__ __half g_w2t[(size_t)DD * FFd];
__device__ __half g_wof[(size_t)DD * DD];

__device__ __forceinline__ void mma_h(uint32_t& d0, uint32_t& d1, const uint32_t* a,
                                      uint32_t b0, uint32_t b1, uint32_t c0, uint32_t c1) {
    asm volatile(
        "mma.sync.aligned.m16n8k16.row.col.f16.f16.f16.f16 "
        "{%0,%1}, {%2,%3,%4,%5}, {%6,%7}, {%8,%9};"
        : "=r"(d0), "=r"(d1)
        : "r"(a[0]), "r"(a[1]), "r"(a[2]), "r"(a[3]), "r"(b0), "r"(b1), "r"(c0), "r"(c1));
}
__device__ __forceinline__ void cp16(void* dst, const void* src) {
    uint32_t d = (uint32_t)__cvta_generic_to_shared(dst);
    asm volatile("cp.async.cg.shared.global [%0], [%1], 16;" :: "r"(d), "l"(src));
}

// ================= f16 GEMM: C[M,N] = A[M,K] @ B[N,K]^T =================
// CTA 128x128, 8 warps (4x2), warp tile 32x64. K-slab 64, 4-deep f16 chains.
#define HSTR 72
#define HT_ELE (128 * HSTR)
#define GEMMH_SMEM (4 * HT_ELE * 2)  // 73728 B -> 2 CTAs/SM fit in 228KB

// EPI: 0 fp32 out ; 1 bias+GELU -> f16 ; 2 (opt bias)+residual -> fp32 ; 3 plain f16
template <int EPI>
__global__ __launch_bounds__(256, 2) void gemm_h(
    const __half* __restrict__ A, int lda,
    const __half* __restrict__ B, int ldb,
    float* __restrict__ C, __half* __restrict__ Ch, int ldc,
    int N, int K,
    const float* __restrict__ bias, const float* __restrict__ res, int ldres)
{
    extern __shared__ __half smh[];
    __half* As = smh;
    __half* Bs = smh + 2 * HT_ELE;
    const int tid = threadIdx.x, lane = tid & 31, warp = tid >> 5;
    const int wm = warp >> 1, wn = warp & 1;
    const int bm0 = blockIdx.y * 128, bn0 = blockIdx.x * 128;
    const int g = lane >> 2, t = lane & 3;

    float acc[2][8][4];
#pragma unroll
    for (int i = 0; i < 2; i++)
#pragma unroll
        for (int j = 0; j < 8; j++)
#pragma unroll
            for (int c = 0; c < 4; c++) acc[i][j][c] = 0.f;

    const int KT = K / 64;
    auto load_tiles = [&](int buf, int k0) {
        __half* Ab = As + buf * HT_ELE;
        __half* Bb = Bs + buf * HT_ELE;
#pragma unroll
        for (int i = 0; i < 4; i++) {
            int idx = i * 256 + tid;
            int r = idx >> 3, s = idx & 7;
            cp16(Ab + r * HSTR + s * 8, A + (size_t)(bm0 + r) * lda + k0 + s * 8);
        }
#pragma unroll
        for (int i = 0; i < 4; i++) {
            int idx = i * 256 + tid;
            int r = idx >> 3, s = idx & 7;
            cp16(Bb + r * HSTR + s * 8, B + (size_t)(bn0 + r) * ldb + k0 + s * 8);
        }
        asm volatile("cp.async.commit_group;");
    };

    load_tiles(0, 0);
    int buf = 0;
    for (int kt = 0; kt < KT; kt++) {
        if (kt + 1 < KT) {
            load_tiles(buf ^ 1, (kt + 1) * 64);
            asm volatile("cp.async.wait_group 1;");
        } else {
            asm volatile("cp.async.wait_group 0;");
        }
        __syncthreads();
        const __half* Ab = As + buf * HT_ELE;
        const __half* Bb = Bs + buf * HT_ELE;

        uint32_t af[4][2][4];
#pragma unroll
        for (int ks = 0; ks < 4; ks++) {
            const int kb = ks * 16 + 2 * t;
#pragma unroll
            for (int im = 0; im < 2; im++) {
                const int r = wm * 32 + im * 16 + g;
                af[ks][im][0] = *(const uint32_t*)(Ab + r * HSTR + kb);
                af[ks][im][1] = *(const uint32_t*)(Ab + (r + 8) * HSTR + kb);
                af[ks][im][2] = *(const uint32_t*)(Ab + r * HSTR + kb + 8);
                af[ks][im][3] = *(const uint32_t*)(Ab + (r + 8) * HSTR + kb + 8);
            }
        }
#pragma unroll
        for (int nt = 0; nt < 8; nt++) {
            const int c = wn * 64 + nt * 8 + g;
            uint32_t bf[4][2];
#pragma unroll
            for (int ks = 0; ks < 4; ks++) {
                const int kb = ks * 16 + 2 * t;
                bf[ks][0] = *(const uint32_t*)(Bb + c * HSTR + kb);
                bf[ks][1] = *(const uint32_t*)(Bb + c * HSTR + kb + 8);
            }
#pragma unroll
            for (int im = 0; im < 2; im++) {
                uint32_t d0 = 0u, d1 = 0u;
#pragma unroll
                for (int ks = 0; ks < 4; ks++)
                    mma_h(d0, d1, af[ks][im], bf[ks][0], bf[ks][1], d0, d1);
                float2 p0 = __half22float2(*reinterpret_cast<__half2*>(&d0));
                float2 p1 = __half22float2(*reinterpret_cast<__half2*>(&d1));
                acc[im][nt][0] += p0.x;
                acc[im][nt][1] += p0.y;
                acc[im][nt][2] += p1.x;
                acc[im][nt][3] += p1.y;
            }
        }
        __syncthreads();
        buf ^= 1;
    }
#pragma unroll
    for (int im = 0; im < 2; im++)
#pragma unroll
        for (int nt = 0; nt < 8; nt++) {
            const int r0 = bm0 + wm * 32 + im * 16 + g;
            const int c0 = bn0 + wn * 64 + nt * 8 + 2 * t;
#pragma unroll
            for (int e = 0; e < 4; e++) {
                int r = r0 + (e >> 1) * 8;
                int c = c0 + (e & 1);
                if (c < N) {
                    float v = acc[im][nt][e];
                    if (EPI == 0) {
                        C[(size_t)r * ldc + c] = v;
                    } else if (EPI == 1) {
                        v += bias[c];
                        v = 0.5f * v * (1.f + erff(v * 0.7071067811865475f));
                        Ch[(size_t)r * ldc + c] = __float2half_rn(v);
                    } else if (EPI == 2) {
                        if (bias) v += bias[c];
                        v += res[(size_t)r * ldres + c];
                        C[(size_t)r * ldc + c] = v;
                    } else {
                        Ch[(size_t)r * ldc + c] = __float2half_rn(v);
                    }
                }
            }
        }
}

// ================= LayerNorm -> f16 =================
__global__ void ln_h_kernel(const float* __restrict__ in, int ldin, int cols,
                            const float* __restrict__ w, const float* __restrict__ b,
                            __half* __restrict__ out, int ldout, int padto)
{
    extern __shared__ float sbuf[];
    __shared__ float red[8];
    __shared__ float bc[2];
    const int row = blockIdx.x, tid = threadIdx.x, lane = tid & 31, warp = tid >> 5;
    const float* ip = in + (size_t)row * ldin;
    float s = 0.f;
    for (int c = tid; c < cols; c += 256) { float v = ip[c]; sbuf[c] = v; s += v; }
#pragma unroll
    for (int o = 16; o > 0; o >>= 1) s += __shfl_xor_sync(0xffffffffu, s, o);
    if (lane == 0) red[warp] = s;
    __syncthreads();
    if (tid == 0) { float t = 0; for (int i = 0; i < 8; i++) t += red[i]; bc[0] = t / cols; }
    __syncthreads();
    float mean = bc[0], vs = 0.f;
    for (int c = tid; c < cols; c += 256) { float d = sbuf[c] - mean; vs += d * d; }
#pragma unroll
    for (int o = 16; o > 0; o >>= 1) vs += __shfl_xor_sync(0xffffffffu, vs, o);
    if (lane == 0) red[warp] = vs;
    __syncthreads();
    if (tid == 0) { float t = 0; for (int i = 0; i < 8; i++) t += red[i]; bc[1] = rsqrtf(t / cols + 1e-5f); }
    __syncthreads();
    float inv = bc[1];
    __half* op = out + (size_t)row * ldout;
    for (int c = tid; c < cols; c += 256) op[c] = __float2half_rn((sbuf[c] - mean) * inv * w[c] + b[c]);
    for (int c = cols + tid; c < padto; c += 256) op[c] = __float2half_rn(0.f);
}

__global__ void freqs_kernel() {
    int j = threadIdx.x;
    if (j < 32) g_freqs[j] = (float)exp(-(double)j * 0.14391156831212787);
}

// [K,N] fp32 -> [Npad,Kpad] f16 transpose-convert, zero-padded. Grid: (Kpad/32, Npad/32)
__global__ void tconv_h_kernel(const float* __restrict__ in, int K, int N, int Kpad,
                               __half* __restrict__ out)
{
    __shared__ float tb[32][33];
    const int k0 = blockIdx.x * 32, n0 = blockIdx.y * 32;
    const int tx = threadIdx.x, ty = threadIdx.y;
#pragma unroll
    for (int i = 0; i < 32; i += 8) {
        int k = k0 + ty + i, n = n0 + tx;
        tb[ty + i][tx] = (k < K && n < N) ? in[(size_t)k * N + n] : 0.f;
    }
    __syncthreads();
#pragma unroll
    for (int i = 0; i < 32; i += 8)
        out[(size_t)(n0 + ty + i) * Kpad + k0 + tx] = __float2half_rn(tb[tx][ty + i]);
}

__global__ void wof_kernel(const float* __restrict__ in, __half* __restrict__ out) {
    size_t i = (size_t)blockIdx.x * blockDim.x + threadIdx.x;
    if (i < (size_t)DD * DD) out[i] = __float2half_rn(in[i]);
}

__global__ void rope_q_kernel(const __half* __restrict__ qraw, __half* __restrict__ qout) {
    int bs = blockIdx.x;
    int s = bs & (SS - 1), b = bs >> 11;
    for (int i = threadIdx.x; i < DD; i += 256) {
        int hh = i >> 7, d = i & 127;
        const __half* src = qraw + (size_t)bs * DD + hh * 128;
        float v;
        if (d < 64) {
            v = __half2float(src[d]);
        } else {
            int dd = d - 64;
            int j = dd & 31;
            float t = (float)s * g_freqs[j];
            float x = __half2float(src[64 + dd]);
            float rx = (dd < 32) ? -__half2float(src[64 + dd + 32]) : __half2float(src[64 + dd - 32]);
            v = x * cosf(t) + rx * sinf(t);
        }
        qout[(((size_t)b * HH + hh) * SS + s) * 128 + d] = __float2half_rn(v);
    }
}

__global__ void reorder_kv_kernel(const __half* __restrict__ kvraw, const float* __restrict__ ckv,
                                  __half* __restrict__ kout, __half* __restrict__ vout) {
    __shared__ float kr[64];
    int bs = blockIdx.x;
    int s = bs & (SS - 1), b = bs >> 11;
    int tid = threadIdx.x;
    if (tid < 64) {
        int dd = tid, j = dd & 31;
        float t = (float)s * g_freqs[j];
        const float* src = ckv + (size_t)bs * CKVN + KVPd;
        float x = src[dd];
        float rx = (dd < 32) ? -src[dd + 32] : src[dd - 32];
        kr[dd] = x * cosf(t) + rx * sinf(t);
    }
    __syncthreads();
    for (int i = tid; i < HH * 192; i += 256) {
        int hh = i / 192, d = i % 192;
        __half v = kvraw[(size_t)bs * 3072 + i];
        size_t base = (((size_t)b * HH + hh) * SS + s) * 128;
        if (d < 64) kout[base + d] = v;
        else vout[base + (d - 64)] = v;
    }
    for (int i = tid; i < HH * 64; i += 256) {
        int hh = i >> 6, dd = i & 63;
        kout[(((size_t)b * HH + hh) * SS + s) * 128 + 64 + dd] = __float2half_rn(kr[dd]);
    }
}

// V [bh][s][128] -> Vt [bh][d][s]
__global__ void vtrans_kernel(const __half* __restrict__ in, __half* __restrict__ out) {
    __shared__ __half tb[32][33];
    const int bh = blockIdx.z;
    const int d0 = blockIdx.x * 32, s0 = blockIdx.y * 32;
    const __half* ib = in + (size_t)bh * SS * 128;
    __half* ob = out + (size_t)bh * 128 * SS;
    const int tx = threadIdx.x, ty = threadIdx.y;
#pragma unroll
    for (int i = 0; i < 32; i += 8)
        tb[ty + i][tx] = ib[(size_t)(s0 + ty + i) * 128 + d0 + tx];
    __syncthreads();
#pragma unroll
    for (int i = 0; i < 32; i += 8)
        ob[(size_t)(d0 + ty + i) * SS + s0 + tx] = tb[tx][ty + i];
}

// ================= attention (all f16 mma), outputs f16 =================
#define QSTRh 136
#define VSTRh 40
#define PSTRh 40
#define ATTN_SMEM ((64 * QSTRh + 32 * QSTRh + 128 * VSTRh + 4 * 16 * PSTRh) * 2)

__global__ __launch_bounds__(128) void attn_kernel(
    const __half* __restrict__ Q, const __half* __restrict__ Kk,
    const __half* __restrict__ Vt, __half* __restrict__ O)
{
    extern __shared__ __half smh[];
    __half* qs = smh;
    __half* ks = qs + 64 * QSTRh;
    __half* vs = ks + 32 * QSTRh;
    __half* ps = vs + 128 * VSTRh;
    const int qb = blockIdx.x, bh = blockIdx.y;
    const int b = bh >> 4, h = bh & 15;
    const int tid = threadIdx.x, lane = tid & 31, w = tid >> 5;
    const int g = lane >> 2, t = lane & 3;
    const int rb = w * 16;

    const __half* Qb = Q + ((size_t)bh * SS + qb * 64) * 128;
    const __half* Kb = Kk + (size_t)bh * SS * 128;
    const __half* Vb = Vt + (size_t)bh * 128 * SS;

#pragma unroll
    for (int i = 0; i < 8; i++) {
        int idx = i * 128 + tid;
        int r = idx >> 4, ss = idx & 15;
        cp16(qs + r * QSTRh + ss * 8, Qb + r * 128 + ss * 8);
    }
    asm volatile("cp.async.commit_group;");
    asm volatile("cp.async.wait_group 0;");
    __syncthreads();

    float m_[2] = {-1e30f, -1e30f};
    float l_[2] = {0.f, 0.f};
    float o[16][4];
#pragma unroll
    for (int i = 0; i < 16; i++)
#pragma unroll
        for (int c = 0; c < 4; c++) o[i][c] = 0.f;

    const int nkt = qb * 2 + 2;
    const float scale = 0.08838834764831845f;
    __half* pw = ps + w * 16 * PSTRh;

    uint32_t af[8][4];
#pragma unroll
    for (int k8 = 0; k8 < 8; k8++) {
        const int kb = k8 * 16 + 2 * t;
        af[k8][0] = *(const uint32_t*)(qs + (rb + g) * QSTRh + kb);
        af[k8][1] = *(const uint32_t*)(qs + (rb + g + 8) * QSTRh + kb);
        af[k8][2] = *(const uint32_t*)(qs + (rb + g) * QSTRh + kb + 8);
        af[k8][3] = *(const uint32_t*)(qs + (rb + g + 8) * QSTRh + kb + 8);
    }

    for (int kt = 0; kt < nkt; kt++) {
#pragma unroll
        for (int i = 0; i < 4; i++) {
            int idx = i * 128 + tid;
            int r = idx >> 4, ss = idx & 15;
            cp16(ks + r * QSTRh + ss * 8, Kb + (size_t)(kt * 32 + r) * 128 + ss * 8);
        }
#pragma unroll
        for (int i = 0; i < 4; i++) {
            int idx = i * 128 + tid;
            int d = idx >> 2, ss = idx & 3;
            cp16(vs + d * VSTRh + ss * 8, Vb + (size_t)d * SS + kt * 32 + ss * 8);
        }
        asm volatile("cp.async.commit_group;");
        asm volatile("cp.async.wait_group 0;");
        __syncthreads();

        float s[4][4];
#pragma unroll
        for (int nt = 0; nt < 4; nt++) {
            uint32_t d0 = 0u, d1 = 0u;
#pragma unroll
            for (int k8 = 0; k8 < 8; k8++) {
                const int kb = k8 * 16 + 2 * t;
                uint32_t b0 = *(const uint32_t*)(ks + (nt * 8 + g) * QSTRh + kb);
                uint32_t b1 = *(const uint32_t*)(ks + (nt * 8 + g) * QSTRh + kb + 8);
                mma_h(d0, d1, af[k8], b0, b1, d0, d1);
            }
            float2 p0 = __half22float2(*reinterpret_cast<__half2*>(&d0));
            float2 p1 = __half22float2(*reinterpret_cast<__half2*>(&d1));
            s[nt][0] = p0.x; s[nt][1] = p0.y; s[nt][2] = p1.x; s[nt][3] = p1.y;
        }

        const int qrow0 = qb * 64 + w * 16 + g;
        const int qrow1 = qrow0 + 8;
#pragma unroll
        for (int nt = 0; nt < 4; nt++)
#pragma unroll
            for (int c = 0; c < 4; c++) {
                int row = (c < 2) ? qrow0 : qrow1;
                int kidx = kt * 32 + nt * 8 + 2 * t + (c & 1);
                float v = s[nt][c] * scale;
                if (kidx > row) v = -1e30f;
                s[nt][c] = v;
            }

        float mx0 = -1e30f, mx1 = -1e30f;
#pragma unroll
        for (int nt = 0; nt < 4; nt++) {
            mx0 = fmaxf(mx0, fmaxf(s[nt][0], s[nt][1]));
            mx1 = fmaxf(mx1, fmaxf(s[nt][2], s[nt][3]));
        }
#pragma unroll
        for (int off = 1; off < 4; off <<= 1) {
            mx0 = fmaxf(mx0, __shfl_xor_sync(0xffffffffu, mx0, off));
            mx1 = fmaxf(mx1, __shfl_xor_sync(0xffffffffu, mx1, off));
        }
        float mn0 = fmaxf(m_[0], mx0), mn1 = fmaxf(m_[1], mx1);
        float al0 = expf(m_[0] - mn0), al1 = expf(m_[1] - mn1);
        float rs0 = 0.f, rs1 = 0.f;
#pragma unroll
        for (int nt = 0; nt < 4; nt++) {
            s[nt][0] = expf(s[nt][0] - mn0);
            s[nt][1] = expf(s[nt][1] - mn0);
            s[nt][2] = expf(s[nt][2] - mn1);
            s[nt][3] = expf(s[nt][3] - mn1);
            rs0 += s[nt][0] + s[nt][1];
            rs1 += s[nt][2] + s[nt][3];
        }
#pragma unroll
        for (int off = 1; off < 4; off <<= 1) {
            rs0 += __shfl_xor_sync(0xffffffffu, rs0, off);
            rs1 += __shfl_xor_sync(0xffffffffu, rs1, off);
        }
        l_[0] = l_[0] * al0 + rs0;
        l_[1] = l_[1] * al1 + rs1;
        m_[0] = mn0; m_[1] = mn1;
#pragma unroll
        for (int nt = 0; nt < 16; nt++) {
            o[nt][0] *= al0; o[nt][1] *= al0;
            o[nt][2] *= al1; o[nt][3] *= al1;
        }

#pragma unroll
        for (int nt = 0; nt < 4; nt++) {
            *reinterpret_cast<__half2*>(pw + g * PSTRh + nt * 8 + 2 * t) =
                __floats2half2_rn(s[nt][0], s[nt][1]);
            *reinterpret_cast<__half2*>(pw + (g + 8) * PSTRh + nt * 8 + 2 * t) =
                __floats2half2_rn(s[nt][2], s[nt][3]);
        }
        __syncwarp();

        uint32_t pf[2][4];
#pragma unroll
        for (int ks2 = 0; ks2 < 2; ks2++) {
            const int kb = ks2 * 16 + 2 * t;
            pf[ks2][0] = *(const uint32_t*)(pw + g * PSTRh + kb);
            pf[ks2][1] = *(const uint32_t*)(pw + (g + 8) * PSTRh + kb);
            pf[ks2][2] = *(const uint32_t*)(pw + g * PSTRh + kb + 8);
            pf[ks2][3] = *(const uint32_t*)(pw + (g + 8) * PSTRh + kb + 8);
        }
#pragma unroll
        for (int nt = 0; nt < 16; nt++) {
            const int col = nt * 8 + g;
            uint32_t b00 = *(const uint32_t*)(vs + col * VSTRh + 2 * t);
            uint32_t b01 = *(const uint32_t*)(vs + col * VSTRh + 2 * t + 8);
            uint32_t b10 = *(const uint32_t*)(vs + col * VSTRh + 16 + 2 * t);
            uint32_t b11 = *(const uint32_t*)(vs + col * VSTRh + 16 + 2 * t + 8);
            uint32_t d0, d1, e0, e1;
            mma_h(d0, d1, pf[0], b00, b01, 0u, 0u);
            mma_h(e0, e1, pf[1], b10, b11, d0, d1);
            float2 p0 = __half22float2(*reinterpret_cast<__half2*>(&e0));
            float2 p1 = __half22float2(*reinterpret_cast<__half2*>(&e1));
            o[nt][0] += p0.x;
            o[nt][1] += p0.y;
            o[nt][2] += p1.x;
            o[nt][3] += p1.y;
        }
        __syncwarp();
        __syncthreads();
    }

    float inv0 = 1.f / l_[0], inv1 = 1.f / l_[1];
    const size_t gr0 = (size_t)b * SS + qb * 64 + w * 16 + g;
#pragma unroll
    for (int nt = 0; nt < 16; nt++) {
        int col = h * 128 + nt * 8 + 2 * t;
        O[gr0 * DD + col] = __float2half_rn(o[nt][0] * inv0);
        O[gr0 * DD + col + 1] = __float2half_rn(o[nt][1] * inv0);
        O[(gr0 + 8) * DD + col] = __float2half_rn(o[nt][2] * inv1);
        O[(gr0 + 8) * DD + col + 1] = __float2half_rn(o[nt][3] * inv1);
    }
}

extern "C" void kernel_launch(void* const* d_in, const int* in_sizes, int n_in,
                              void* d_out, int out_size)
{
    (void)in_sizes; (void)n_in; (void)out_size;
    const float* x    = (const float*)d_in[0];
    const float* anw  = (const float*)d_in[1];
    const float* anb  = (const float*)d_in[2];
    const float* Wdq  = (const float*)d_in[3];
    const float* qlw  = (const float*)d_in[4];
    const float* qlb  = (const float*)d_in[5];
    const float* Wuq  = (const float*)d_in[6];
    const float* Wdkv = (const float*)d_in[7];
    const float* klw  = (const float*)d_in[8];
    const float* klb  = (const float*)d_in[9];
    const float* Wukv = (const float*)d_in[10];
    const float* Wo   = (const float*)d_in[11];
    const float* fnw  = (const float*)d_in[12];
    const float* fnb  = (const float*)d_in[13];
    const float* W1   = (const float*)d_in[14];
    const float* b1   = (const float*)d_in[15];
    const float* W2   = (const float*)d_in[16];
    const float* b2   = (const float*)d_in[17];

    float* out = (float*)d_out;
    float* ckv = out + (size_t)MMr * DD;

    float *pcq, *px2;
    __half *phf, *pcqf, *pkvlf, *pof, *pff1f, *pqrawh, *pkvrawh, *pqh, *pkh, *pvtmp, *pvT;
    __half *pdqt, *pdkvt, *puqt, *pukvt, *pw1t, *pw2t, *pwof;
    cudaGetSymbolAddress((void**)&pcq, g_cq);
    cudaGetSymbolAddress((void**)&px2, g_x2);
    cudaGetSymbolAddress((void**)&phf, g_hf);
    cudaGetSymbolAddress((void**)&pcqf, g_cqf);
    cudaGetSymbolAddress((void**)&pkvlf, g_kvlf);
    cudaGetSymbolAddress((void**)&pof, g_of);
    cudaGetSymbolAddress((void**)&pff1f, g_ff1f);
    cudaGetSymbolAddress((void**)&pqrawh, g_qrawh);
    cudaGetSymbolAddress((void**)&pkvrawh, g_kvrawh);
    cudaGetSymbolAddress((void**)&pqh, g_qh);
    cudaGetSymbolAddress((void**)&pkh, g_kh);
    cudaGetSymbolAddress((void**)&pvtmp, g_vtmp);
    cudaGetSymbolAddress((void**)&pvT, g_vT);
    cudaGetSymbolAddress((void**)&pdqt, g_dqt);
    cudaGetSymbolAddress((void**)&pdkvt, g_dkvt);
    cudaGetSymbolAddress((void**)&puqt, g_uqt);
    cudaGetSymbolAddress((void**)&pukvt, g_ukvt);
    cudaGetSymbolAddress((void**)&pw1t, g_w1t);
    cudaGetSymbolAddress((void**)&pw2t, g_w2t);
    cudaGetSymbolAddress((void**)&pwof, g_wof);

    cudaFuncSetAttribute(gemm_h<0>, cudaFuncAttributeMaxDynamicSharedMemorySize, GEMMH_SMEM);
    cudaFuncSetAttribute(gemm_h<1>, cudaFuncAttributeMaxDynamicSharedMemorySize, GEMMH_SMEM);
    cudaFuncSetAttribute(gemm_h<2>, cudaFuncAttributeMaxDynamicSharedMemorySize, GEMMH_SMEM);
    cudaFuncSetAttribute(gemm_h<3>, cudaFuncAttributeMaxDynamicSharedMemorySize, GEMMH_SMEM);
    cudaFuncSetAttribute(attn_kernel, cudaFuncAttributeMaxDynamicSharedMemorySize, ATTN_SMEM);

    dim3 blk(256);
    dim3 t32x8(32, 8);
    freqs_kernel<<<1, 32>>>();
    ln_h_kernel<<<MMr, 256, DD * 4>>>(x, DD, DD, anw, anb, phf, DD, DD);
    tconv_h_kernel<<<dim3(64, 32), t32x8>>>(Wdq, DD, QPd, DD, pdqt);
    tconv_h_kernel<<<dim3(64, 48), t32x8>>>(Wdkv, DD, CKVN, DD, pdkvt);
    tconv_h_kernel<<<dim3(32, 64), t32x8>>>(Wuq, QPd, DD, QPd, puqt);
    tconv_h_kernel<<<dim3(44, 96), t32x8>>>(Wukv, KVPd, 3072, KVL_PAD, pukvt);
    tconv_h_kernel<<<dim3(64, 256), t32x8>>>(W1, DD, FFd, DD, pw1t);
    tconv_h_kernel<<<dim3(256, 64), t32x8>>>(W2, FFd, DD, FFd, pw2t);
    wof_kernel<<<(DD * DD + 255) / 256, 256>>>(Wo, pwof);

    // cq_raw = h @ W_dq (fp32: feeds LN stats)
    gemm_h<0><<<dim3(QPd / 128, MMr / 128), blk, GEMMH_SMEM>>>(
        phf, DD, pdqt, DD, pcq, nullptr, QPd, QPd, DD, nullptr, nullptr, 0);
    // ckv = h @ W_dkv (fp32 output, N=1429 guarded)
    gemm_h<0><<<dim3(DKV_NPAD / 128, MMr / 128), blk, GEMMH_SMEM>>>(
        phf, DD, pdkvt, DD, ckv, nullptr, CKVN, CKVN, DD, nullptr, nullptr, 0);
    ln_h_kernel<<<MMr, 256, QPd * 4>>>(pcq, QPd, QPd, qlw, qlb, pcqf, QPd, QPd);
    ln_h_kernel<<<MMr, 256, KVPd * 4>>>(ckv, CKVN, KVPd, klw, klb, pkvlf, KVL_PAD, KVL_PAD);
    // Q_raw = cq @ W_uq -> f16
    gemm_h<3><<<dim3(DD / 128, MMr / 128), blk, GEMMH_SMEM>>>(
        pcqf, QPd, puqt, QPd, nullptr, pqrawh, DD, DD, QPd, nullptr, nullptr, 0);
    // KV_raw = kv_lora @ W_ukv -> f16
    gemm_h<3><<<dim3(3072 / 128, MMr / 128), blk, GEMMH_SMEM>>>(
        pkvlf, KVL_PAD, pukvt, KVL_PAD, nullptr, pkvrawh, 3072, 3072, KVL_PAD, nullptr, nullptr, 0);

    rope_q_kernel<<<MMr, 256>>>(pqrawh, pqh);
    reorder_kv_kernel<<<MMr, 256>>>(pkvrawh, ckv, pkh, pvtmp);
    vtrans_kernel<<<dim3(4, 64, BB * HH), t32x8>>>(pvtmp, pvT);
    attn_kernel<<<dim3(SS / 64, BB * HH), 128, ATTN_SMEM>>>(pqh, pkh, pvT, pof);

    // x2 = x + o @ Wo^T
    gemm_h<2><<<dim3(DD / 128, MMr / 128), blk, GEMMH_SMEM>>>(
        pof, DD, pwof, DD, px2, nullptr, DD, DD, DD, nullptr, x, DD);
    ln_h_kernel<<<MMr, 256, DD * 4>>>(px2, DD, DD, fnw, fnb, phf, DD, DD);
    // ff1 = gelu(h @ W1 + b1) -> f16
    gemm_h<1><<<dim3(FFd / 128, MMr / 128), blk, GEMMH_SMEM>>>(
        phf, DD, pw1t, DD, nullptr, pff1f, FFd, FFd, DD, b1, nullptr, 0);
    // out = x2 + ff1 @ W2 + b2
    gemm_h<2><<<dim3(DD / 128, MMr / 128), blk, GEMMH_SMEM>>>(
        pff1f, FFd, pw2t, FFd, out, nullptr, DD, DD, FFd, b2, px2, DD);
}